// round 11
// baseline (speedup 1.0000x reference)
#include <cuda_runtime.h>
#include <math.h>
#include <mma.h>

using namespace nvcuda;

// Problem dims
#define BB   64
#define C2   35
#define RR   (BB*C2)     // 2240 rows
#define TIN  512
#define TT   256
#define NE   70
#define ED   32
#define MOE_BLOCKS 296

// ---------------- scratch (device globals; no runtime allocation) ----------------
__device__ __align__(16) float d_gw[TIN*TT];
__device__ __align__(16) float d_gb[TT];
__device__ __align__(16) float d_cn[2*NE*ED];
__device__ __align__(16) float d_gl[RR*TT];
__device__ __align__(16) float d_gr[RR*TT];
__device__ __align__(16) float d_q [RR*TT];
__device__ __align__(16) float d_k [RR*TT];
__device__ __align__(16) float d_v [RR*TT];
__device__ __align__(16) float d_tl[RR*TT];
__device__ __align__(16) float d_tr[RR*TT];
__device__ __align__(16) float d_al[RR*TT];
__device__ __align__(16) float d_ar[RR*TT];
__device__ int   d_e1[RR];
__device__ int   d_e2[RR];
__device__ int   d_cnt[NE];
__device__ int   d_list[NE*RR];
__device__ int2  d_chunks[512];
__device__ int   d_nch;
__device__ __align__(16) float d_pl0[RR*TT];
__device__ __align__(16) float d_pl1[RR*TT];
__device__ __align__(16) float d_pr0[RR*TT];
__device__ __align__(16) float d_pr1[RR*TT];
__device__ __align__(16) float d_p1[40*64*256];
__device__ __align__(16) float d_h2[64*256];
__device__ __align__(16) float d_h3[64*32];

// ---------------- helpers ----------------
__device__ __forceinline__ float warpSumDown(float v){
#pragma unroll
    for (int o=16;o>0;o>>=1) v += __shfl_down_sync(0xffffffffu, v, o);
    return v;
}
__device__ __forceinline__ float warpSumAll(float v){
#pragma unroll
    for (int o=16;o>0;o>>=1) v += __shfl_xor_sync(0xffffffffu, v, o);
    return v;
}
__device__ __forceinline__ float eluf(float x){ return x > 0.f ? x : expm1f(x); }

__device__ __forceinline__ float blockSum256(float v, float* red, float* bc){
    const int n = threadIdx.x, wid = n >> 5;
    float s = warpSumDown(v);
    if ((n & 31) == 0) red[wid] = s;
    __syncthreads();
    if (n < 32){
        float t = (n < 8) ? red[n] : 0.f;
        t = warpSumDown(t);
        if (n == 0) *bc = t;
    }
    __syncthreads();
    float r = *bc;
    __syncthreads();
    return r;
}

// ---------------- prep ----------------
__global__ void prep_gw(const float* __restrict__ GW, const float* __restrict__ GB){
    int idx = blockIdx.x*256 + threadIdx.x;
    d_gw[idx] = GW[idx] + GW[idx + TIN*TT];
    if (idx < TT) d_gb[idx] = -(GB[idx] + GB[idx+TT]);
}

__global__ void normc(const float* __restrict__ C){
    int b = blockIdx.x;
    int lane = threadIdx.x;
    float c = C[b*ED + lane];
    float ss = warpSumAll(c*c);
    d_cn[b*ED + lane] = c / fmaxf(sqrtf(ss), 1e-12f);
}

__global__ void mclr(int* cnt){ if (threadIdx.x < NE) cnt[threadIdx.x] = 0; }

__global__ void mkchunks(const int* __restrict__ cnt){
    if (threadIdx.x == 0){
        int t = 0;
        for (int e = 0; e < NE; e++){
            int n = cnt[e];
            for (int s = 0; s < n; s += 16) d_chunks[t++] = make_int2(e, s);
        }
        d_nch = t;
    }
}

// ---------------- 3xTF32 tensor-core GEMM (+bias,+relu,+LN,+res), z-batched -------
// C_z(M x 256) = [LN](act((A_z [- A2_z]) @ W_z + bias_z)) [+ res_z]
// BM=32, BN=256, K-block 8. block 256 (8 warps): wm=wid&1 (16-row grp),
// wn=wid>>1 (64-col grp, 4 n-frags). Split a = ah + al (tf32 each); 3 MMAs.
struct GemmArgs {
    const float* A[3];
    const float* A2[3];
    const float* W[3];
    const float* bias[3];
    const float* lng[3];
    const float* lnb[3];
    const float* res[3];
    float*       C[3];
};

__global__ __launch_bounds__(256) void gemmT(GemmArgs args, int K, int relu)
{
    const int z = blockIdx.y;
    const float* __restrict__ A    = args.A[z];
    const float* __restrict__ A2   = args.A2[z];
    const float* __restrict__ W    = args.W[z];
    const float* __restrict__ bias = args.bias[z];
    const float* __restrict__ lng  = args.lng[z];
    const float* __restrict__ lnb  = args.lnb[z];
    const float* __restrict__ res  = args.res[z];
    float* __restrict__ C          = args.C[z];

    __shared__ float sA[8][40];      // [k][m]
    __shared__ float sB[8][264];     // [k][n]
    __shared__ float sC[32][264];

    const int tid = threadIdx.x;
    const int wid = tid >> 5;
    const int lane = tid & 31;
    const int wm = wid & 1;          // row group (16 rows)
    const int wn = wid >> 1;         // col group (64 cols)
    const int m0 = blockIdx.x << 5;

    wmma::fragment<wmma::accumulator,16,16,8,float> acc[4];
#pragma unroll
    for (int f=0;f<4;f++) wmma::fill_fragment(acc[f], 0.f);

    for (int kb = 0; kb < K; kb += 8){
        // A tile 32x8 -> sA[k][m]
        if (tid < 64){
            int r = tid & 31, kq = (tid >> 5) << 2;
            const size_t off = (size_t)(m0+r)*K + kb + kq;
            float4 v = *(const float4*)(A + off);
            if (A2){
                float4 u = *(const float4*)(A2 + off);
                v.x -= u.x; v.y -= u.y; v.z -= u.z; v.w -= u.w;
            }
            sA[kq+0][r]=v.x; sA[kq+1][r]=v.y; sA[kq+2][r]=v.z; sA[kq+3][r]=v.w;
        }
        // B tile 8x256 -> sB[k][n]; 512 float4, 2 per thread
#pragma unroll
        for (int i = tid; i < 512; i += 256){
            int kk = i >> 6, cq = (i & 63) << 2;
            *(float4*)&sB[kk][cq] = *(const float4*)(W + (size_t)(kb+kk)*256 + cq);
        }
        __syncthreads();

        wmma::fragment<wmma::matrix_a,16,16,8,wmma::precision::tf32,wmma::col_major> fah, fal;
        wmma::load_matrix_sync(fah, &sA[0][wm*16], 40);
#pragma unroll
        for (int t=0;t<fah.num_elements;t++){
            float a = fah.x[t];
            float h = wmma::__float_to_tf32(a);
            fal.x[t] = wmma::__float_to_tf32(a - h);
            fah.x[t] = h;
        }
#pragma unroll
        for (int nf = 0; nf < 4; nf++){
            wmma::fragment<wmma::matrix_b,16,16,8,wmma::precision::tf32,wmma::row_major> fbh, fbl;
            wmma::load_matrix_sync(fbh, &sB[0][wn*64 + nf*16], 264);
#pragma unroll
            for (int t=0;t<fbh.num_elements;t++){
                float b = fbh.x[t];
                float h = wmma::__float_to_tf32(b);
                fbl.x[t] = wmma::__float_to_tf32(b - h);
                fbh.x[t] = h;
            }
            wmma::mma_sync(acc[nf], fah, fbh, acc[nf]);
            wmma::mma_sync(acc[nf], fah, fbl, acc[nf]);
            wmma::mma_sync(acc[nf], fal, fbh, acc[nf]);
        }
        __syncthreads();
    }

#pragma unroll
    for (int nf = 0; nf < 4; nf++)
        wmma::store_matrix_sync(&sC[wm*16][wn*64 + nf*16], acc[nf], 264, wmma::mem_row_major);
    __syncthreads();

    // epilogue: warp wid handles rows wid*4..+3; lane handles 8 contiguous cols
    const int c0 = lane << 3;
    float bcol[8];
    {
        float4 b0 = *(const float4*)(bias + c0);
        float4 b1 = *(const float4*)(bias + c0 + 4);
        bcol[0]=b0.x; bcol[1]=b0.y; bcol[2]=b0.z; bcol[3]=b0.w;
        bcol[4]=b1.x; bcol[5]=b1.y; bcol[6]=b1.z; bcol[7]=b1.w;
    }
    float gcol[8], qcol[8];
    if (lng){
        float4 g0 = *(const float4*)(lng + c0);
        float4 g1 = *(const float4*)(lng + c0 + 4);
        float4 q0 = *(const float4*)(lnb + c0);
        float4 q1 = *(const float4*)(lnb + c0 + 4);
        gcol[0]=g0.x; gcol[1]=g0.y; gcol[2]=g0.z; gcol[3]=g0.w;
        gcol[4]=g1.x; gcol[5]=g1.y; gcol[6]=g1.z; gcol[7]=g1.w;
        qcol[0]=q0.x; qcol[1]=q0.y; qcol[2]=q0.z; qcol[3]=q0.w;
        qcol[4]=q1.x; qcol[5]=q1.y; qcol[6]=q1.z; qcol[7]=q1.w;
    }

#pragma unroll
    for (int i=0;i<4;i++){
        const int r = wid*4 + i;
        const int row = m0 + r;
        float v[8];
#pragma unroll
        for (int j=0;j<8;j++){
            v[j] = sC[r][c0+j] + bcol[j];
            if (relu) v[j] = fmaxf(v[j], 0.f);
        }
        if (lng){
            float s = 0.f;
#pragma unroll
            for (int j=0;j<8;j++) s += v[j];
            float mean = warpSumAll(s) * (1.f/256.f);
            float sq = 0.f;
#pragma unroll
            for (int j=0;j<8;j++){ float d = v[j]-mean; sq += d*d; }
            float inv = rsqrtf(warpSumAll(sq) * (1.f/256.f) + 1e-5f);
#pragma unroll
            for (int j=0;j<8;j++) v[j] = (v[j]-mean)*inv*gcol[j] + qcol[j];
            if (res){
                float4 r0 = *(const float4*)(res + (size_t)row*256 + c0);
                float4 r1 = *(const float4*)(res + (size_t)row*256 + c0 + 4);
                v[0]+=r0.x; v[1]+=r0.y; v[2]+=r0.z; v[3]+=r0.w;
                v[4]+=r1.x; v[5]+=r1.y; v[6]+=r1.z; v[7]+=r1.w;
            }
        }
        *(float4*)(C + (size_t)row*256 + c0)     = make_float4(v[0],v[1],v[2],v[3]);
        *(float4*)(C + (size_t)row*256 + c0 + 4) = make_float4(v[4],v[5],v[6],v[7]);
    }
}

// ---------------- attention (35 tokens per batch, 1 head), y-split ----------------
__global__ __launch_bounds__(256) void attn35(
    const float* __restrict__ Q, const float* __restrict__ Km,
    const float* __restrict__ V, float* __restrict__ TL, float* __restrict__ TR)
{
    __shared__ float sk[35*256];
    __shared__ float S[35*36];
    const int b = blockIdx.x, tid = threadIdx.x;
    const int r0 = blockIdx.y * 18, r1 = min(35, r0 + 18);
    const size_t base = (size_t)b * (35*256);
    for (int i=tid;i<35*256;i+=256) sk[i] = Km[base+i];
    __syncthreads();
    for (int e=tid;e<1225;e+=256){
        int r = e/35, c = e - r*35;
        const float* qr = Q + base + r*256;
        const float* kr = &sk[c*256];
        float s = 0.f;
#pragma unroll 8
        for (int k=0;k<256;k++) s += qr[k]*kr[k];
        S[r*36+c] = s * 0.0625f;
    }
    __syncthreads();
    if (tid < 35){
        float mx = -1e30f;
        for (int c=0;c<35;c++) mx = fmaxf(mx, S[tid*36+c]);
        float sum = 0.f;
        for (int c=0;c<35;c++){ float e = expf(S[tid*36+c]-mx); S[tid*36+c]=e; sum+=e; }
        float inv = 1.f/sum;
        for (int c=0;c<35;c++) S[tid*36+c] *= inv;
    }
    __syncthreads();
    for (int i=tid;i<35*256;i+=256) sk[i] = V[base+i];
    __syncthreads();
    const int n = tid;
    for (int r=r0;r<r1;r++){
        float al=0.f, ar=0.f;
#pragma unroll
        for (int k=0;k<35;k++){
            float vv = sk[k*256+n];
            al += S[r*36+k]*vv;
            ar += S[k*36+r]*vv;
        }
        TL[base + r*256 + n] = al;
        TR[base + r*256 + n] = ar;
    }
}

// ---------------- router + cosine top-2; appends to expert lists ----------------
__global__ __launch_bounds__(128) void route(
    const float* __restrict__ AL, const float* __restrict__ AR,
    const float* __restrict__ RW, const float* __restrict__ RB,
    const float* __restrict__ CN, int* __restrict__ E1, int* __restrict__ E2,
    int* __restrict__ cnt, int* __restrict__ list)
{
    __shared__ float sx[512];
    __shared__ float part[4][32];
    __shared__ float sz[32];
    __shared__ float ssim[70];
    const int row = blockIdx.x, tid = threadIdx.x;
    for (int i=tid;i<256;i+=128){
        sx[i]     = AL[(size_t)row*256+i];
        sx[256+i] = AR[(size_t)row*256+i];
    }
    __syncthreads();
    {
        const int o = tid & 31, p = tid >> 5;
        float acc = (p == 0) ? RB[o] : 0.f;
        for (int k = p*128; k < p*128+128; k++) acc += sx[k]*RW[k*32+o];
        part[p][o] = acc;
    }
    __syncthreads();
    if (tid < 32){
        float acc = part[0][tid]+part[1][tid]+part[2][tid]+part[3][tid];
        float n2 = warpSumAll(acc*acc);
        sz[tid] = acc / fmaxf(sqrtf(n2), 1e-12f);
    }
    __syncthreads();
    if (tid < 70){
        const float* c = CN + tid*32;
        float s = 0.f;
#pragma unroll
        for (int j=0;j<32;j++) s += sz[j]*c[j];
        ssim[tid] = s;
    }
    __syncthreads();
    if (tid == 0){
        float m1=-2.f; int i1=0;
        for (int e=0;e<70;e++) if (ssim[e] > m1){ m1=ssim[e]; i1=e; }
        float m2=-2.f; int i2=(i1==0)?1:0;
        for (int e=0;e<70;e++) if (e!=i1 && ssim[e] > m2){ m2=ssim[e]; i2=e; }
        E1[row]=i1; E2[row]=i2;
        int p1 = atomicAdd(&cnt[i1], 1);
        list[i1*RR + p1] = row;                 // slot 0
        int p2 = atomicAdd(&cnt[i2], 1);
        list[i2*RR + p2] = row | (1 << 15);     // slot 1
    }
}

// ---------------- grouped MoE GEMM over FLAT chunk list (perfect balance) ---------
__global__ __launch_bounds__(256) void moeGrp(
    const float* __restrict__ AL, const float* __restrict__ AR,
    const float* __restrict__ EW,
    const int* __restrict__ cnt, const int* __restrict__ list,
    float* __restrict__ PL0, float* __restrict__ PL1,
    float* __restrict__ PR0, float* __restrict__ PR1)
{
    __shared__ float sA[16][36];
    __shared__ float sB[16][256];
    __shared__ int sent[16];

    const int tid = threadIdx.x;
    const int tx = tid & 31, ty = tid >> 5;
    const int c0 = tx << 2;
    const int nch = d_nch;

    for (int ci = blockIdx.x; ci < nch; ci += gridDim.x){
        const int2 ch = d_chunks[ci];
        const int e = ch.x;
        const int n = cnt[e];
        const float* __restrict__ W = EW + (size_t)e*65536;

        __syncthreads();
        if (tid < 16){
            int idx = ch.y + tid;
            sent[tid] = (idx < n) ? list[e*RR + idx] : -1;
        }
        __syncthreads();

        float acc[4][8] = {};
        for (int kb = 0; kb < 256; kb += 16){
            if (tid < 128){
                int r = tid >> 2, kq = (tid & 3) << 2;
                int ent = sent[r & 15];
                float4 v = make_float4(0.f,0.f,0.f,0.f);
                if (ent >= 0){
                    int row = ent & 0x7FFF;
                    const float* src = (r < 16) ? AL : AR;
                    v = *(const float4*)(src + (size_t)row*256 + kb + kq);
                }
                sA[kq+0][r]=v.x; sA[kq+1][r]=v.y; sA[kq+2][r]=v.z; sA[kq+3][r]=v.w;
            }
#pragma unroll
            for (int i = tid; i < 1024; i += 256){
                int kk = i >> 6, cq = (i & 63) << 2;
                *(float4*)&sB[kk][cq] = *(const float4*)(W + (size_t)(kb+kk)*256 + cq);
            }
            __syncthreads();
#pragma unroll
            for (int k = 0; k < 16; k++){
                float a0 = sA[k][ty*4+0], a1 = sA[k][ty*4+1];
                float a2 = sA[k][ty*4+2], a3 = sA[k][ty*4+3];
                float4 bl = *(float4*)&sB[k][c0];
                float4 bh = *(float4*)&sB[k][c0+128];
                acc[0][0]+=a0*bl.x; acc[0][1]+=a0*bl.y; acc[0][2]+=a0*bl.z; acc[0][3]+=a0*bl.w;
                acc[0][4]+=a0*bh.x; acc[0][5]+=a0*bh.y; acc[0][6]+=a0*bh.z; acc[0][7]+=a0*bh.w;
                acc[1][0]+=a1*bl.x; acc[1][1]+=a1*bl.y; acc[1][2]+=a1*bl.z; acc[1][3]+=a1*bl.w;
                acc[1][4]+=a1*bh.x; acc[1][5]+=a1*bh.y; acc[1][6]+=a1*bh.z; acc[1][7]+=a1*bh.w;
                acc[2][0]+=a2*bl.x; acc[2][1]+=a2*bl.y; acc[2][2]+=a2*bl.z; acc[2][3]+=a2*bl.w;
                acc[2][4]+=a2*bh.x; acc[2][5]+=a2*bh.y; acc[2][6]+=a2*bh.z; acc[2][7]+=a2*bh.w;
                acc[3][0]+=a3*bl.x; acc[3][1]+=a3*bl.y; acc[3][2]+=a3*bl.z; acc[3][3]+=a3*bl.w;
                acc[3][4]+=a3*bh.x; acc[3][5]+=a3*bh.y; acc[3][6]+=a3*bh.z; acc[3][7]+=a3*bh.w;
            }
            __syncthreads();
        }

#pragma unroll
        for (int i=0;i<4;i++){
            int r = ty*4 + i;
            int ent = sent[r & 15];
            if (ent >= 0){
                int row = ent & 0x7FFF, slot = ent >> 15;
                float* dst = (r < 16) ? (slot ? PL1 : PL0) : (slot ? PR1 : PR0);
                *(float4*)(dst + (size_t)row*256 + c0) =
                    make_float4(acc[i][0],acc[i][1],acc[i][2],acc[i][3]);
                *(float4*)(dst + (size_t)row*256 + c0 + 128) =
                    make_float4(acc[i][4],acc[i][5],acc[i][6],acc[i][7]);
            }
        }
    }
}

// ---------------- MoE combine: partials + bias -> LN -> +residual (both sides) ----
__global__ __launch_bounds__(256) void moeC(
    const float* __restrict__ AL, const float* __restrict__ AR,
    const float* __restrict__ PL0, const float* __restrict__ PL1,
    const float* __restrict__ PR0, const float* __restrict__ PR1,
    const float* __restrict__ EB,
    const int* __restrict__ E1, const int* __restrict__ E2,
    const float* __restrict__ g0, const float* __restrict__ b0,
    const float* __restrict__ g1, const float* __restrict__ b1,
    float* __restrict__ GL, float* __restrict__ GR)
{
    __shared__ float red[8];
    __shared__ float bc;
    const int row = blockIdx.x, n = threadIdx.x;
    const size_t off = (size_t)row*256 + n;
    const int e1 = E1[row], e2 = E2[row];
    const float bb = EB[e1*256+n] + EB[e2*256+n];
    const float a  = AL[off], b = AR[off];
    float ml = PL0[off] + PL1[off] + bb;
    float mr = PR0[off] + PR1[off] + bb;

    float mean = blockSum256(ml, red, &bc) * (1.f/256.f);
    float dd = ml - mean;
    float var = blockSum256(dd*dd, red, &bc) * (1.f/256.f);
    GL[off] = dd * rsqrtf(var + 1e-5f) * g0[n] + b0[n] + a;

    mean = blockSum256(mr, red, &bc) * (1.f/256.f);
    dd = mr - mean;
    var = blockSum256(dd*dd, red, &bc) * (1.f/256.f);
    GR[off] = dd * rsqrtf(var + 1e-5f) * g1[n] + b1[n] + b;
}

// ---------------- classifier fc1: split-K partial GEMM ----------------
__global__ __launch_bounds__(256) void fc1part(
    const float* __restrict__ GL, const float* __restrict__ GR,
    const float* __restrict__ W, float* __restrict__ P)
{
    __shared__ float As[16][64];
    __shared__ float Bs[16][64];
    const int s = blockIdx.y;
    const float* A = (s < 20) ? (GL + s*448) : (GR + (s-20)*448);
    const int n0 = blockIdx.x << 6;
    const int wk0 = s*448;
    const int tid = threadIdx.x;
    const int tx = tid & 15, ty = tid >> 4;
    const int lar = tid >> 2, laq = tid & 3;
    const int lbk = tid >> 4, lbc = tid & 15;
    float acc[4][4] = {};
    for (int kb = 0; kb < 448; kb += 16){
        float4 av = *(const float4*)(A + (size_t)lar*8960 + kb + laq*4);
        As[laq*4+0][lar] = av.x; As[laq*4+1][lar] = av.y;
        As[laq*4+2][lar] = av.z; As[laq*4+3][lar] = av.w;
        *(float4*)&Bs[lbk][lbc*4] =
            *(const float4*)(W + (size_t)(wk0+kb+lbk)*256 + n0 + lbc*4);
        __syncthreads();
#pragma unroll
        for (int k = 0; k < 16; k++){
            float4 a = *(const float4*)&As[k][ty*4];
            float4 b = *(const float4*)&Bs[k][tx*4];
            acc[0][0] += a.x*b.x; acc[0][1] += a.x*b.y; acc[0][2] += a.x*b.z; acc[0][3] += a.x*b.w;
            acc[1][0] += a.y*b.x; acc[1][1] += a.y*b.y; acc[1][2] += a.y*b.z; acc[1][3] += a.y*b.w;
            acc[2][0] += a.z*b.x; acc[2][1] += a.z*b.y; acc[2][2] += a.z*b.z; acc[2][3] += a.z*b.w;
            acc[3][0] += a.w*b.x; acc[3][1] += a.w*b.y; acc[3][2] += a.w*b.z; acc[3][3] += a.w*b.w;
        }
        __syncthreads();
    }
#pragma unroll
    for (int i=0;i<4;i++)
#pragma unroll
        for (int j=0;j<4;j++)
            P[(size_t)s*16384 + (size_t)(ty*4+i)*256 + n0 + tx*4 + j] = acc[i][j];
}

__global__ __launch_bounds__(256) void fc1red(
    const float* __restrict__ P, const float* __restrict__ bias,
    float* __restrict__ H2)
{
    const int b = blockIdx.x, n = threadIdx.x;
    float acc = bias[n];
    for (int s=0;s<40;s++) acc += P[(size_t)s*16384 + b*256 + n];
    H2[b*256+n] = eluf(acc);
}

__global__ void fc2k(const float* __restrict__ H2, const float* __restrict__ W,
                     const float* __restrict__ bias, float* __restrict__ H3)
{
    const int b = blockIdx.x, j = threadIdx.x;
    float acc = bias[j];
    for (int k=0;k<256;k++) acc += H2[b*256+k] * W[k*32+j];
    H3[b*32+j] = eluf(acc);
}

__global__ void fc3k(const float* __restrict__ H3, const float* __restrict__ W,
                     const float* __restrict__ bias, float* __restrict__ OUT)
{
    const int tid = threadIdx.x;
    const int b = tid/3, c = tid%3;
    float acc = bias[c];
#pragma unroll
    for (int k=0;k<32;k++) acc += H3[b*32+k] * W[k*3+c];
    OUT[b*3+c] = acc;
}

// ---------------- host launch sequence ----------------
extern "C" void kernel_launch(void* const* d_in, const int* in_sizes, int n_in,
                              void* d_out, int out_size)
{
    const float* x_l      = (const float*)d_in[0];
    const float* x_r      = (const float*)d_in[1];
    const float* gcn_w    = (const float*)d_in[2];
    const float* gcn_b    = (const float*)d_in[3];
    const float* bln_g    = (const float*)d_in[4];
    const float* bln_b    = (const float*)d_in[5];
    const float* attn_w   = (const float*)d_in[6];
    const float* attn_b   = (const float*)d_in[7];
    const float* aln_g    = (const float*)d_in[8];
    const float* aln_b    = (const float*)d_in[9];
    const float* router_w = (const float*)d_in[10];
    const float* router_b = (const float*)d_in[11];
    const float* centers  = (const float*)d_in[12];
    const float* expert_w = (const float*)d_in[13];
    const float* expert_b = (const float*)d_in[14];
    const float* mln_g    = (const float*)d_in[15];
    const float* mln_b    = (const float*)d_in[16];
    const float* fc1_w    = (const float*)d_in[17];
    const float* fc1_b    = (const float*)d_in[18];
    const float* fc2_w    = (const float*)d_in[19];
    const float* fc2_b    = (const float*)d_in[20];
    const float* fc3_w    = (const float*)d_in[21];
    const float* fc3_b    = (const float*)d_in[22];
    float* out = (float*)d_out;

    float *gw, *gb, *cn, *gl, *gr, *q, *k, *v, *tl, *tr, *al, *ar;
    float *pl0, *pl1, *pr0, *pr1, *p1, *h2, *h3;
    int *e1, *e2, *cnt, *list;
    cudaGetSymbolAddress((void**)&gw,  d_gw);
    cudaGetSymbolAddress((void**)&gb,  d_gb);
    cudaGetSymbolAddress((void**)&cn,  d_cn);
    cudaGetSymbolAddress((void**)&gl,  d_gl);
    cudaGetSymbolAddress((void**)&gr,  d_gr);
    cudaGetSymbolAddress((void**)&q,   d_q);
    cudaGetSymbolAddress((void**)&k,   d_k);
    cudaGetSymbolAddress((void**)&v,   d_v);
    cudaGetSymbolAddress((void**)&tl,  d_tl);
    cudaGetSymbolAddress((void**)&tr,  d_tr);
    cudaGetSymbolAddress((void**)&al,  d_al);
    cudaGetSymbolAddress((void**)&ar,  d_ar);
    cudaGetSymbolAddress((void**)&pl0, d_pl0);
    cudaGetSymbolAddress((void**)&pl1, d_pl1);
    cudaGetSymbolAddress((void**)&pr0, d_pr0);
    cudaGetSymbolAddress((void**)&pr1, d_pr1);
    cudaGetSymbolAddress((void**)&p1,  d_p1);
    cudaGetSymbolAddress((void**)&h2,  d_h2);
    cudaGetSymbolAddress((void**)&h3,  d_h3);
    cudaGetSymbolAddress((void**)&e1,  d_e1);
    cudaGetSymbolAddress((void**)&e2,  d_e2);
    cudaGetSymbolAddress((void**)&cnt, d_cnt);
    cudaGetSymbolAddress((void**)&list,d_list);

    // prep
    prep_gw<<<512, 256>>>(gcn_w, gcn_b);
    normc<<<2*NE, 32>>>(centers);

    // BiDGN: gcn + relu + LN fused, both sides in one launch (3xTF32 TC)
    {
        GemmArgs a = {};
        a.A[0] = x_l;  a.A[1] = x_r;
        a.W[0] = gw;   a.W[1] = gw;
        a.bias[0] = gb; a.bias[1] = gb;
        a.lng[0] = bln_g; a.lng[1] = bln_g;
        a.lnb[0] = bln_b; a.lnb[1] = bln_b;
        a.C[0] = gl;  a.C[1] = gr;
        gemmT<<<dim3(RR/32, 2), 256>>>(a, TIN, 1);
    }

    for (int i = 0; i < 2; i++){
        const float* Wq = attn_w + (size_t)(i*4+0)*TT*TT;
        const float* Wk = attn_w + (size_t)(i*4+1)*TT*TT;
        const float* Wv = attn_w + (size_t)(i*4+2)*TT*TT;
        const float* Wp = attn_w + (size_t)(i*4+3)*TT*TT;
        const float* bq = attn_b + (i*4+0)*TT;
        const float* bk = attn_b + (i*4+1)*TT;
        const float* bv = attn_b + (i*4+2)*TT;
        const float* bp = attn_b + (i*4+3)*TT;

        {   // Q, K, V in one launch (V input fused: gl - gr); 3xTF32 TC
            GemmArgs a = {};
            a.A[0] = gl; a.A[1] = gr; a.A[2] = gl;
            a.A2[2] = gr;
            a.W[0] = Wq; a.W[1] = Wk; a.W[2] = Wv;
            a.bias[0] = bq; a.bias[1] = bk; a.bias[2] = bv;
            a.C[0] = q; a.C[1] = k; a.C[2] = v;
            gemmT<<<dim3(RR/32, 3), 256>>>(a, TT, 0);
        }
        attn35<<<dim3(BB, 2), 256>>>(q, k, v, tl, tr);
        {   // proj + LN + residual for both sides in one launch; 3xTF32 TC
            GemmArgs a = {};
            a.A[0] = tl; a.A[1] = tr;
            a.W[0] = Wp; a.W[1] = Wp;
            a.bias[0] = bp; a.bias[1] = bp;
            a.lng[0] = aln_g + (i*2+0)*TT; a.lng[1] = aln_g + (i*2+1)*TT;
            a.lnb[0] = aln_b + (i*2+0)*TT; a.lnb[1] = aln_b + (i*2+1)*TT;
            a.res[0] = gl; a.res[1] = gr;
            a.C[0] = al; a.C[1] = ar;
            gemmT<<<dim3(RR/32, 2), 256>>>(a, TT, 0);
        }

        mclr<<<1, 128>>>(cnt);
        route<<<RR, 128>>>(al, ar, router_w + (size_t)i*TIN*ED, router_b + i*ED,
                           cn + i*NE*ED, e1, e2, cnt, list);
        mkchunks<<<1, 32>>>(cnt);
        moeGrp<<<MOE_BLOCKS, 256>>>(al, ar, expert_w + (size_t)i*NE*TT*TT,
                                    cnt, list, pl0, pl1, pr0, pr1);
        moeC<<<RR, 256>>>(al, ar, pl0, pl1, pr0, pr1,
                          expert_b + (size_t)i*NE*TT, e1, e2,
                          mln_g + (i*2+0)*TT, mln_b + (i*2+0)*TT,
                          mln_g + (i*2+1)*TT, mln_b + (i*2+1)*TT,
                          gl, gr);
    }

    // classifier head
    fc1part<<<dim3(4,40), 256>>>(gl, gr, fc1_w, p1);
    fc1red<<<BB, 256>>>(p1, fc1_b, h2);
    fc2k<<<BB, 32>>>(h2, fc2_w, fc2_b, h3);
    fc3k<<<1, 192>>>(h3, fc3_w, fc3_b, out);
}

// round 12
// speedup vs baseline: 1.2518x; 1.2518x over previous
#include <cuda_runtime.h>
#include <math.h>

// Problem dims
#define BB   64
#define C2   35
#define RR   (BB*C2)     // 2240 rows
#define TIN  512
#define TT   256
#define NE   70
#define ED   32
#define MOE_BLOCKS 296

// ---------------- scratch (device globals; no runtime allocation) ----------------
__device__ __align__(16) float d_gw[TIN*TT];
__device__ __align__(16) float d_gb[TT];
__device__ __align__(16) float d_cn[2*NE*ED];
__device__ __align__(16) float d_gl[RR*TT];
__device__ __align__(16) float d_gr[RR*TT];
__device__ __align__(16) float d_q [RR*TT];
__device__ __align__(16) float d_k [RR*TT];
__device__ __align__(16) float d_v [RR*TT];
__device__ __align__(16) float d_tl[RR*TT];
__device__ __align__(16) float d_tr[RR*TT];
__device__ __align__(16) float d_al[RR*TT];
__device__ __align__(16) float d_ar[RR*TT];
__device__ int   d_e1[RR];
__device__ int   d_e2[RR];
__device__ int   d_cnt[NE];
__device__ int   d_list[NE*RR];
__device__ int2  d_chunks[512];
__device__ int   d_nch;
__device__ __align__(16) float d_pl0[RR*TT];
__device__ __align__(16) float d_pl1[RR*TT];
__device__ __align__(16) float d_pr0[RR*TT];
__device__ __align__(16) float d_pr1[RR*TT];
__device__ __align__(16) float d_p1[40*64*256];
__device__ __align__(16) float d_h2[64*256];
__device__ __align__(16) float d_h3[64*32];

// ---------------- helpers ----------------
__device__ __forceinline__ float warpSumDown(float v){
#pragma unroll
    for (int o=16;o>0;o>>=1) v += __shfl_down_sync(0xffffffffu, v, o);
    return v;
}
__device__ __forceinline__ float warpSumAll(float v){
#pragma unroll
    for (int o=16;o>0;o>>=1) v += __shfl_xor_sync(0xffffffffu, v, o);
    return v;
}
__device__ __forceinline__ float eluf(float x){ return x > 0.f ? x : expm1f(x); }

__device__ __forceinline__ float blockSum256(float v, float* red, float* bc){
    const int n = threadIdx.x, wid = n >> 5;
    float s = warpSumDown(v);
    if ((n & 31) == 0) red[wid] = s;
    __syncthreads();
    if (n < 32){
        float t = (n < 8) ? red[n] : 0.f;
        t = warpSumDown(t);
        if (n == 0) *bc = t;
    }
    __syncthreads();
    float r = *bc;
    __syncthreads();
    return r;
}

// ---------------- prep ----------------
__global__ void prep_gw(const float* __restrict__ GW, const float* __restrict__ GB){
    int idx = blockIdx.x*256 + threadIdx.x;
    d_gw[idx] = GW[idx] + GW[idx + TIN*TT];
    if (idx < TT) d_gb[idx] = -(GB[idx] + GB[idx+TT]);
}

__global__ void normc(const float* __restrict__ C){
    int b = blockIdx.x;
    int lane = threadIdx.x;
    float c = C[b*ED + lane];
    float ss = warpSumAll(c*c);
    d_cn[b*ED + lane] = c / fmaxf(sqrtf(ss), 1e-12f);
}

__global__ void mclr(int* cnt){ if (threadIdx.x < NE) cnt[threadIdx.x] = 0; }

__global__ void mkchunks(const int* __restrict__ cnt){
    if (threadIdx.x == 0){
        int t = 0;
        for (int e = 0; e < NE; e++){
            int n = cnt[e];
            for (int s = 0; s < n; s += 16) d_chunks[t++] = make_int2(e, s);
        }
        d_nch = t;
    }
}

// ---------------- fused GEMM (+bias,+relu,+LN,+residual), z-batched, BM=32/BN=256 --
// Software-pipelined: tile k+1 prefetched into registers during compute of tile k.
struct GemmArgs {
    const float* A[3];
    const float* A2[3];
    const float* W[3];
    const float* bias[3];
    const float* lng[3];
    const float* lnb[3];
    const float* res[3];
    float*       C[3];
};

__global__ __launch_bounds__(256) void gemmF(GemmArgs args, int K, int relu)
{
    const int z = blockIdx.y;
    const float* __restrict__ A    = args.A[z];
    const float* __restrict__ A2   = args.A2[z];
    const float* __restrict__ W    = args.W[z];
    const float* __restrict__ bias = args.bias[z];
    const float* __restrict__ lng  = args.lng[z];
    const float* __restrict__ lnb  = args.lnb[z];
    const float* __restrict__ res  = args.res[z];
    float* __restrict__ C          = args.C[z];

    __shared__ float sA[16][36];
    __shared__ float sB[16][256];

    const int tid = threadIdx.x;
    const int tx = tid & 31, ty = tid >> 5;
    const int m0 = blockIdx.x << 5;
    const int c0 = tx << 2;
    const int ar_ = tid >> 2, akq = (tid & 3) << 2;      // A-load mapping (tid<128)

    float acc[4][8] = {};
    float4 rA;
    float4 rB[4];

    // preload tile 0
    if (tid < 128){
        const size_t off = (size_t)(m0+ar_)*K + akq;
        rA = *(const float4*)(A + off);
        if (A2){
            float4 u = *(const float4*)(A2 + off);
            rA.x -= u.x; rA.y -= u.y; rA.z -= u.z; rA.w -= u.w;
        }
    }
#pragma unroll
    for (int j = 0; j < 4; j++){
        int i = tid + j*256;
        int kk = i >> 6, cq = (i & 63) << 2;
        rB[j] = *(const float4*)(W + (size_t)kk*256 + cq);
    }

    for (int kb = 0; kb < K; kb += 16){
        if (tid < 128){
            sA[akq+0][ar_]=rA.x; sA[akq+1][ar_]=rA.y;
            sA[akq+2][ar_]=rA.z; sA[akq+3][ar_]=rA.w;
        }
#pragma unroll
        for (int j = 0; j < 4; j++){
            int i = tid + j*256;
            int kk = i >> 6, cq = (i & 63) << 2;
            *(float4*)&sB[kk][cq] = rB[j];
        }
        __syncthreads();

        // prefetch next tile
        if (kb + 16 < K){
            if (tid < 128){
                const size_t off = (size_t)(m0+ar_)*K + kb + 16 + akq;
                rA = *(const float4*)(A + off);
                if (A2){
                    float4 u = *(const float4*)(A2 + off);
                    rA.x -= u.x; rA.y -= u.y; rA.z -= u.z; rA.w -= u.w;
                }
            }
#pragma unroll
            for (int j = 0; j < 4; j++){
                int i = tid + j*256;
                int kk = i >> 6, cq = (i & 63) << 2;
                rB[j] = *(const float4*)(W + (size_t)(kb+16+kk)*256 + cq);
            }
        }

#pragma unroll
        for (int k = 0; k < 16; k++){
            float a0 = sA[k][ty*4+0], a1 = sA[k][ty*4+1];
            float a2 = sA[k][ty*4+2], a3 = sA[k][ty*4+3];
            float4 bl = *(float4*)&sB[k][c0];
            float4 bh = *(float4*)&sB[k][c0+128];
            acc[0][0]+=a0*bl.x; acc[0][1]+=a0*bl.y; acc[0][2]+=a0*bl.z; acc[0][3]+=a0*bl.w;
            acc[0][4]+=a0*bh.x; acc[0][5]+=a0*bh.y; acc[0][6]+=a0*bh.z; acc[0][7]+=a0*bh.w;
            acc[1][0]+=a1*bl.x; acc[1][1]+=a1*bl.y; acc[1][2]+=a1*bl.z; acc[1][3]+=a1*bl.w;
            acc[1][4]+=a1*bh.x; acc[1][5]+=a1*bh.y; acc[1][6]+=a1*bh.z; acc[1][7]+=a1*bh.w;
            acc[2][0]+=a2*bl.x; acc[2][1]+=a2*bl.y; acc[2][2]+=a2*bl.z; acc[2][3]+=a2*bl.w;
            acc[2][4]+=a2*bh.x; acc[2][5]+=a2*bh.y; acc[2][6]+=a2*bh.z; acc[2][7]+=a2*bh.w;
            acc[3][0]+=a3*bl.x; acc[3][1]+=a3*bl.y; acc[3][2]+=a3*bl.z; acc[3][3]+=a3*bl.w;
            acc[3][4]+=a3*bh.x; acc[3][5]+=a3*bh.y; acc[3][6]+=a3*bh.z; acc[3][7]+=a3*bh.w;
        }
        __syncthreads();
    }

    float4 bl = *(const float4*)(bias + c0);
    float4 bh = *(const float4*)(bias + c0 + 128);
    float bcol[8] = {bl.x,bl.y,bl.z,bl.w,bh.x,bh.y,bh.z,bh.w};

    float gcol[8], bbcol[8];
    if (lng){
        float4 g0 = *(const float4*)(lng + c0);
        float4 g1 = *(const float4*)(lng + c0 + 128);
        float4 q0 = *(const float4*)(lnb + c0);
        float4 q1 = *(const float4*)(lnb + c0 + 128);
        gcol[0]=g0.x; gcol[1]=g0.y; gcol[2]=g0.z; gcol[3]=g0.w;
        gcol[4]=g1.x; gcol[5]=g1.y; gcol[6]=g1.z; gcol[7]=g1.w;
        bbcol[0]=q0.x; bbcol[1]=q0.y; bbcol[2]=q0.z; bbcol[3]=q0.w;
        bbcol[4]=q1.x; bbcol[5]=q1.y; bbcol[6]=q1.z; bbcol[7]=q1.w;
    }

#pragma unroll
    for (int i=0;i<4;i++){
        const int row = m0 + ty*4 + i;
        float v[8];
#pragma unroll
        for (int j=0;j<8;j++){
            v[j] = acc[i][j] + bcol[j];
            if (relu) v[j] = fmaxf(v[j], 0.f);
        }
        if (lng){
            float s = 0.f;
#pragma unroll
            for (int j=0;j<8;j++) s += v[j];
            float mean = warpSumAll(s) * (1.f/256.f);
            float sq = 0.f;
#pragma unroll
            for (int j=0;j<8;j++){ float d = v[j]-mean; sq += d*d; }
            float inv = rsqrtf(warpSumAll(sq) * (1.f/256.f) + 1e-5f);
#pragma unroll
            for (int j=0;j<8;j++) v[j] = (v[j]-mean)*inv*gcol[j] + bbcol[j];
            if (res){
                float4 r0 = *(const float4*)(res + (size_t)row*256 + c0);
                float4 r1 = *(const float4*)(res + (size_t)row*256 + c0 + 128);
                v[0]+=r0.x; v[1]+=r0.y; v[2]+=r0.z; v[3]+=r0.w;
                v[4]+=r1.x; v[5]+=r1.y; v[6]+=r1.z; v[7]+=r1.w;
            }
        }
        *(float4*)(C + (size_t)row*256 + c0)       = make_float4(v[0],v[1],v[2],v[3]);
        *(float4*)(C + (size_t)row*256 + c0 + 128) = make_float4(v[4],v[5],v[6],v[7]);
    }
}

// ---------------- plain GEMM, BM=32/BN=128 (no LN), pipelined ----------------
__global__ __launch_bounds__(256) void gemmH(GemmArgs args, int K)
{
    const int z = blockIdx.z;
    const float* __restrict__ A    = args.A[z];
    const float* __restrict__ A2   = args.A2[z];
    const float* __restrict__ W    = args.W[z];
    const float* __restrict__ bias = args.bias[z];
    float* __restrict__ C          = args.C[z];

    __shared__ float sA[16][36];
    __shared__ float sB[16][128];

    const int tid = threadIdx.x;
    const int tx = tid & 31, ty = tid >> 5;
    const int m0 = blockIdx.y << 5;
    const int n0 = blockIdx.x << 7;
    const int c0 = tx << 2;
    const int ar_ = tid >> 2, akq = (tid & 3) << 2;

    float acc[4][4] = {};
    float4 rA;
    float4 rB[2];

    if (tid < 128){
        const size_t off = (size_t)(m0+ar_)*K + akq;
        rA = *(const float4*)(A + off);
        if (A2){
            float4 u = *(const float4*)(A2 + off);
            rA.x -= u.x; rA.y -= u.y; rA.z -= u.z; rA.w -= u.w;
        }
    }
#pragma unroll
    for (int j = 0; j < 2; j++){
        int i = tid + j*256;
        int kk = i >> 5, cq = (i & 31) << 2;
        rB[j] = *(const float4*)(W + (size_t)kk*256 + n0 + cq);
    }

    for (int kb = 0; kb < K; kb += 16){
        if (tid < 128){
            sA[akq+0][ar_]=rA.x; sA[akq+1][ar_]=rA.y;
            sA[akq+2][ar_]=rA.z; sA[akq+3][ar_]=rA.w;
        }
#pragma unroll
        for (int j = 0; j < 2; j++){
            int i = tid + j*256;
            int kk = i >> 5, cq = (i & 31) << 2;
            *(float4*)&sB[kk][cq] = rB[j];
        }
        __syncthreads();

        if (kb + 16 < K){
            if (tid < 128){
                const size_t off = (size_t)(m0+ar_)*K + kb + 16 + akq;
                rA = *(const float4*)(A + off);
                if (A2){
                    float4 u = *(const float4*)(A2 + off);
                    rA.x -= u.x; rA.y -= u.y; rA.z -= u.z; rA.w -= u.w;
                }
            }
#pragma unroll
            for (int j = 0; j < 2; j++){
                int i = tid + j*256;
                int kk = i >> 5, cq = (i & 31) << 2;
                rB[j] = *(const float4*)(W + (size_t)(kb+16+kk)*256 + n0 + cq);
            }
        }

#pragma unroll
        for (int k = 0; k < 16; k++){
            float a0 = sA[k][ty*4+0], a1 = sA[k][ty*4+1];
            float a2 = sA[k][ty*4+2], a3 = sA[k][ty*4+3];
            float4 b = *(float4*)&sB[k][c0];
            acc[0][0]+=a0*b.x; acc[0][1]+=a0*b.y; acc[0][2]+=a0*b.z; acc[0][3]+=a0*b.w;
            acc[1][0]+=a1*b.x; acc[1][1]+=a1*b.y; acc[1][2]+=a1*b.z; acc[1][3]+=a1*b.w;
            acc[2][0]+=a2*b.x; acc[2][1]+=a2*b.y; acc[2][2]+=a2*b.z; acc[2][3]+=a2*b.w;
            acc[3][0]+=a3*b.x; acc[3][1]+=a3*b.y; acc[3][2]+=a3*b.z; acc[3][3]+=a3*b.w;
        }
        __syncthreads();
    }

    float4 bv = *(const float4*)(bias + n0 + c0);
#pragma unroll
    for (int i=0;i<4;i++){
        const int row = m0 + ty*4 + i;
        *(float4*)(C + (size_t)row*256 + n0 + c0) =
            make_float4(acc[i][0]+bv.x, acc[i][1]+bv.y, acc[i][2]+bv.z, acc[i][3]+bv.w);
    }
}

// ---------------- attention (35 tokens per batch, 1 head), y-split ----------------
__global__ __launch_bounds__(256) void attn35(
    const float* __restrict__ Q, const float* __restrict__ Km,
    const float* __restrict__ V, float* __restrict__ TL, float* __restrict__ TR)
{
    __shared__ float sk[35*256];
    __shared__ float S[35*36];
    const int b = blockIdx.x, tid = threadIdx.x;
    const int r0 = blockIdx.y * 18, r1 = min(35, r0 + 18);
    const size_t base = (size_t)b * (35*256);
    for (int i=tid;i<35*256;i+=256) sk[i] = Km[base+i];
    __syncthreads();
    for (int e=tid;e<1225;e+=256){
        int r = e/35, c = e - r*35;
        const float* qr = Q + base + r*256;
        const float* kr = &sk[c*256];
        float s = 0.f;
#pragma unroll 8
        for (int k=0;k<256;k++) s += qr[k]*kr[k];
        S[r*36+c] = s * 0.0625f;
    }
    __syncthreads();
    if (tid < 35){
        float mx = -1e30f;
        for (int c=0;c<35;c++) mx = fmaxf(mx, S[tid*36+c]);
        float sum = 0.f;
        for (int c=0;c<35;c++){ float e = expf(S[tid*36+c]-mx); S[tid*36+c]=e; sum+=e; }
        float inv = 1.f/sum;
        for (int c=0;c<35;c++) S[tid*36+c] *= inv;
    }
    __syncthreads();
    for (int i=tid;i<35*256;i+=256) sk[i] = V[base+i];
    __syncthreads();
    const int n = tid;
    for (int r=r0;r<r1;r++){
        float al=0.f, ar=0.f;
#pragma unroll
        for (int k=0;k<35;k++){
            float vv = sk[k*256+n];
            al += S[r*36+k]*vv;
            ar += S[k*36+r]*vv;
        }
        TL[base + r*256 + n] = al;
        TR[base + r*256 + n] = ar;
    }
}

// ---------------- router + cosine top-2; appends to expert lists ----------------
__global__ __launch_bounds__(128) void route(
    const float* __restrict__ AL, const float* __restrict__ AR,
    const float* __restrict__ RW, const float* __restrict__ RB,
    const float* __restrict__ CN, int* __restrict__ E1, int* __restrict__ E2,
    int* __restrict__ cnt, int* __restrict__ list)
{
    __shared__ float sx[512];
    __shared__ float part[4][32];
    __shared__ float sz[32];
    __shared__ float ssim[70];
    const int row = blockIdx.x, tid = threadIdx.x;
    for (int i=tid;i<256;i+=128){
        sx[i]     = AL[(size_t)row*256+i];
        sx[256+i] = AR[(size_t)row*256+i];
    }
    __syncthreads();
    {
        const int o = tid & 31, p = tid >> 5;
        float acc = (p == 0) ? RB[o] : 0.f;
        for (int k = p*128; k < p*128+128; k++) acc += sx[k]*RW[k*32+o];
        part[p][o] = acc;
    }
    __syncthreads();
    if (tid < 32){
        float acc = part[0][tid]+part[1][tid]+part[2][tid]+part[3][tid];
        float n2 = warpSumAll(acc*acc);
        sz[tid] = acc / fmaxf(sqrtf(n2), 1e-12f);
    }
    __syncthreads();
    if (tid < 70){
        const float* c = CN + tid*32;
        float s = 0.f;
#pragma unroll
        for (int j=0;j<32;j++) s += sz[j]*c[j];
        ssim[tid] = s;
    }
    __syncthreads();
    if (tid == 0){
        float m1=-2.f; int i1=0;
        for (int e=0;e<70;e++) if (ssim[e] > m1){ m1=ssim[e]; i1=e; }
        float m2=-2.f; int i2=(i1==0)?1:0;
        for (int e=0;e<70;e++) if (e!=i1 && ssim[e] > m2){ m2=ssim[e]; i2=e; }
        E1[row]=i1; E2[row]=i2;
        int p1 = atomicAdd(&cnt[i1], 1);
        list[i1*RR + p1] = row;                 // slot 0
        int p2 = atomicAdd(&cnt[i2], 1);
        list[i2*RR + p2] = row | (1 << 15);     // slot 1
    }
}

// ---------------- grouped MoE GEMM over FLAT chunk list, pipelined ----------------
__global__ __launch_bounds__(256) void moeGrp(
    const float* __restrict__ AL, const float* __restrict__ AR,
    const float* __restrict__ EW,
    const int* __restrict__ cnt, const int* __restrict__ list,
    float* __restrict__ PL0, float* __restrict__ PL1,
    float* __restrict__ PR0, float* __restrict__ PR1)
{
    __shared__ float sA[16][36];
    __shared__ float sB[16][256];
    __shared__ int sent[16];

    const int tid = threadIdx.x;
    const int tx = tid & 31, ty = tid >> 5;
    const int c0 = tx << 2;
    const int ar_ = tid >> 2, akq = (tid & 3) << 2;
    const int nch = d_nch;

    for (int ci = blockIdx.x; ci < nch; ci += gridDim.x){
        const int2 ch = d_chunks[ci];
        const int e = ch.x;
        const int n = cnt[e];
        const float* __restrict__ W = EW + (size_t)e*65536;

        __syncthreads();
        if (tid < 16){
            int idx = ch.y + tid;
            sent[tid] = (idx < n) ? list[e*RR + idx] : -1;
        }
        __syncthreads();

        float acc[4][8] = {};
        float4 rA = make_float4(0.f,0.f,0.f,0.f);
        float4 rB[4];

        // preload kb = 0
        if (tid < 128){
            int ent = sent[ar_ & 15];
            if (ent >= 0){
                int row = ent & 0x7FFF;
                const float* src = (ar_ < 16) ? AL : AR;
                rA = *(const float4*)(src + (size_t)row*256 + akq);
            }
        }
#pragma unroll
        for (int j = 0; j < 4; j++){
            int i = tid + j*256;
            int kk = i >> 6, cq = (i & 63) << 2;
            rB[j] = *(const float4*)(W + (size_t)kk*256 + cq);
        }

        for (int kb = 0; kb < 256; kb += 16){
            if (tid < 128){
                sA[akq+0][ar_]=rA.x; sA[akq+1][ar_]=rA.y;
                sA[akq+2][ar_]=rA.z; sA[akq+3][ar_]=rA.w;
            }
#pragma unroll
            for (int j = 0; j < 4; j++){
                int i = tid + j*256;
                int kk = i >> 6, cq = (i & 63) << 2;
                *(float4*)&sB[kk][cq] = rB[j];
            }
            __syncthreads();

            if (kb + 16 < 256){
                if (tid < 128){
                    int ent = sent[ar_ & 15];
                    rA = make_float4(0.f,0.f,0.f,0.f);
                    if (ent >= 0){
                        int row = ent & 0x7FFF;
                        const float* src = (ar_ < 16) ? AL : AR;
                        rA = *(const float4*)(src + (size_t)row*256 + kb + 16 + akq);
                    }
                }
#pragma unroll
                for (int j = 0; j < 4; j++){
                    int i = tid + j*256;
                    int kk = i >> 6, cq = (i & 63) << 2;
                    rB[j] = *(const float4*)(W + (size_t)(kb+16+kk)*256 + cq);
                }
            }

#pragma unroll
            for (int k = 0; k < 16; k++){
                float a0 = sA[k][ty*4+0], a1 = sA[k][ty*4+1];
                float a2 = sA[k][ty*4+2], a3 = sA[k][ty*4+3];
                float4 bl = *(float4*)&sB[k][c0];
                float4 bh = *(float4*)&sB[k][c0+128];
                acc[0][0]+=a0*bl.x; acc[0][1]+=a0*bl.y; acc[0][2]+=a0*bl.z; acc[0][3]+=a0*bl.w;
                acc[0][4]+=a0*bh.x; acc[0][5]+=a0*bh.y; acc[0][6]+=a0*bh.z; acc[0][7]+=a0*bh.w;
                acc[1][0]+=a1*bl.x; acc[1][1]+=a1*bl.y; acc[1][2]+=a1*bl.z; acc[1][3]+=a1*bl.w;
                acc[1][4]+=a1*bh.x; acc[1][5]+=a1*bh.y; acc[1][6]+=a1*bh.z; acc[1][7]+=a1*bh.w;
                acc[2][0]+=a2*bl.x; acc[2][1]+=a2*bl.y; acc[2][2]+=a2*bl.z; acc[2][3]+=a2*bl.w;
                acc[2][4]+=a2*bh.x; acc[2][5]+=a2*bh.y; acc[2][6]+=a2*bh.z; acc[2][7]+=a2*bh.w;
                acc[3][0]+=a3*bl.x; acc[3][1]+=a3*bl.y; acc[3][2]+=a3*bl.z; acc[3][3]+=a3*bl.w;
                acc[3][4]+=a3*bh.x; acc[3][5]+=a3*bh.y; acc[3][6]+=a3*bh.z; acc[3][7]+=a3*bh.w;
            }
            __syncthreads();
        }

#pragma unroll
        for (int i=0;i<4;i++){
            int r = ty*4 + i;
            int ent = sent[r & 15];
            if (ent >= 0){
                int row = ent & 0x7FFF, slot = ent >> 15;
                float* dst = (r < 16) ? (slot ? PL1 : PL0) : (slot ? PR1 : PR0);
                *(float4*)(dst + (size_t)row*256 + c0) =
                    make_float4(acc[i][0],acc[i][1],acc[i][2],acc[i][3]);
                *(float4*)(dst + (size_t)row*256 + c0 + 128) =
                    make_float4(acc[i][4],acc[i][5],acc[i][6],acc[i][7]);
            }
        }
    }
}

// ---------------- MoE combine: partials + bias -> LN -> +residual (both sides) ----
__global__ __launch_bounds__(256) void moeC(
    const float* __restrict__ AL, const float* __restrict__ AR,
    const float* __restrict__ PL0, const float* __restrict__ PL1,
    const float* __restrict__ PR0, const float* __restrict__ PR1,
    const float* __restrict__ EB,
    const int* __restrict__ E1, const int* __restrict__ E2,
    const float* __restrict__ g0, const float* __restrict__ b0,
    const float* __restrict__ g1, const float* __restrict__ b1,
    float* __restrict__ GL, float* __restrict__ GR)
{
    __shared__ float red[8];
    __shared__ float bc;
    const int row = blockIdx.x, n = threadIdx.x;
    const size_t off = (size_t)row*256 + n;
    const int e1 = E1[row], e2 = E2[row];
    const float bb = EB[e1*256+n] + EB[e2*256+n];
    const float a  = AL[off], b = AR[off];
    float ml = PL0[off] + PL1[off] + bb;
    float mr = PR0[off] + PR1[off] + bb;

    float mean = blockSum256(ml, red, &bc) * (1.f/256.f);
    float dd = ml - mean;
    float var = blockSum256(dd*dd, red, &bc) * (1.f/256.f);
    GL[off] = dd * rsqrtf(var + 1e-5f) * g0[n] + b0[n] + a;

    mean = blockSum256(mr, red, &bc) * (1.f/256.f);
    dd = mr - mean;
    var = blockSum256(dd*dd, red, &bc) * (1.f/256.f);
    GR[off] = dd * rsqrtf(var + 1e-5f) * g1[n] + b1[n] + b;
}

// ---------------- classifier fc1: split-K partial GEMM ----------------
__global__ __launch_bounds__(256) void fc1part(
    const float* __restrict__ GL, const float* __restrict__ GR,
    const float* __restrict__ W, float* __restrict__ P)
{
    __shared__ float As[16][64];
    __shared__ float Bs[16][64];
    const int s = blockIdx.y;
    const float* A = (s < 20) ? (GL + s*448) : (GR + (s-20)*448);
    const int n0 = blockIdx.x << 6;
    const int wk0 = s*448;
    const int tid = threadIdx.x;
    const int tx = tid & 15, ty = tid >> 4;
    const int lar = tid >> 2, laq = tid & 3;
    const int lbk = tid >> 4, lbc = tid & 15;
    float acc[4][4] = {};
    for (int kb = 0; kb < 448; kb += 16){
        float4 av = *(const float4*)(A + (size_t)lar*8960 + kb + laq*4);
        As[laq*4+0][lar] = av.x; As[laq*4+1][lar] = av.y;
        As[laq*4+2][lar] = av.z; As[laq*4+3][lar] = av.w;
        *(float4*)&Bs[lbk][lbc*4] =
            *(const float4*)(W + (size_t)(wk0+kb+lbk)*256 + n0 + lbc*4);
        __syncthreads();
#pragma unroll
        for (int k = 0; k < 16; k++){
            float4 a = *(const float4*)&As[k][ty*4];
            float4 b = *(const float4*)&Bs[k][tx*4];
            acc[0][0] += a.x*b.x; acc[0][1] += a.x*b.y; acc[0][2] += a.x*b.z; acc[0][3] += a.x*b.w;
            acc[1][0] += a.y*b.x; acc[1][1] += a.y*b.y; acc[1][2] += a.y*b.z; acc[1][3] += a.y*b.w;
            acc[2][0] += a.z*b.x; acc[2][1] += a.z*b.y; acc[2][2] += a.z*b.z; acc[2][3] += a.z*b.w;
            acc[3][0] += a.w*b.x; acc[3][1] += a.w*b.y; acc[3][2] += a.w*b.z; acc[3][3] += a.w*b.w;
        }
        __syncthreads();
    }
#pragma unroll
    for (int i=0;i<4;i++)
#pragma unroll
        for (int j=0;j<4;j++)
            P[(size_t)s*16384 + (size_t)(ty*4+i)*256 + n0 + tx*4 + j] = acc[i][j];
}

__global__ __launch_bounds__(256) void fc1red(
    const float* __restrict__ P, const float* __restrict__ bias,
    float* __restrict__ H2)
{
    const int b = blockIdx.x, n = threadIdx.x;
    float acc = bias[n];
    for (int s=0;s<40;s++) acc += P[(size_t)s*16384 + b*256 + n];
    H2[b*256+n] = eluf(acc);
}

__global__ void fc2k(const float* __restrict__ H2, const float* __restrict__ W,
                     const float* __restrict__ bias, float* __restrict__ H3)
{
    const int b = blockIdx.x, j = threadIdx.x;
    float acc = bias[j];
    for (int k=0;k<256;k++) acc += H2[b*256+k] * W[k*32+j];
    H3[b*32+j] = eluf(acc);
}

__global__ void fc3k(const float* __restrict__ H3, const float* __restrict__ W,
                     const float* __restrict__ bias, float* __restrict__ OUT)
{
    const int tid = threadIdx.x;
    const int b = tid/3, c = tid%3;
    float acc = bias[c];
#pragma unroll
    for (int k=0;k<32;k++) acc += H3[b*32+k] * W[k*3+c];
    OUT[b*3+c] = acc;
}

// ---------------- host launch sequence ----------------
extern "C" void kernel_launch(void* const* d_in, const int* in_sizes, int n_in,
                              void* d_out, int out_size)
{
    const float* x_l      = (const float*)d_in[0];
    const float* x_r      = (const float*)d_in[1];
    const float* gcn_w    = (const float*)d_in[2];
    const float* gcn_b    = (const float*)d_in[3];
    const float* bln_g    = (const float*)d_in[4];
    const float* bln_b    = (const float*)d_in[5];
    const float* attn_w   = (const float*)d_in[6];
    const float* attn_b   = (const float*)d_in[7];
    const float* aln_g    = (const float*)d_in[8];
    const float* aln_b    = (const float*)d_in[9];
    const float* router_w = (const float*)d_in[10];
    const float* router_b = (const float*)d_in[11];
    const float* centers  = (const float*)d_in[12];
    const float* expert_w = (const float*)d_in[13];
    const float* expert_b = (const float*)d_in[14];
    const float* mln_g    = (const float*)d_in[15];
    const float* mln_b    = (const float*)d_in[16];
    const float* fc1_w    = (const float*)d_in[17];
    const float* fc1_b    = (const float*)d_in[18];
    const float* fc2_w    = (const float*)d_in[19];
    const float* fc2_b    = (const float*)d_in[20];
    const float* fc3_w    = (const float*)d_in[21];
    const float* fc3_b    = (const float*)d_in[22];
    float* out = (float*)d_out;

    float *gw, *gb, *cn, *gl, *gr, *q, *k, *v, *tl, *tr, *al, *ar;
    float *pl0, *pl1, *pr0, *pr1, *p1, *h2, *h3;
    int *e1, *e2, *cnt, *list;
    cudaGetSymbolAddress((void**)&gw,  d_gw);
    cudaGetSymbolAddress((void**)&gb,  d_gb);
    cudaGetSymbolAddress((void**)&cn,  d_cn);
    cudaGetSymbolAddress((void**)&gl,  d_gl);
    cudaGetSymbolAddress((void**)&gr,  d_gr);
    cudaGetSymbolAddress((void**)&q,   d_q);
    cudaGetSymbolAddress((void**)&k,   d_k);
    cudaGetSymbolAddress((void**)&v,   d_v);
    cudaGetSymbolAddress((void**)&tl,  d_tl);
    cudaGetSymbolAddress((void**)&tr,  d_tr);
    cudaGetSymbolAddress((void**)&al,  d_al);
    cudaGetSymbolAddress((void**)&ar,  d_ar);
    cudaGetSymbolAddress((void**)&pl0, d_pl0);
    cudaGetSymbolAddress((void**)&pl1, d_pl1);
    cudaGetSymbolAddress((void**)&pr0, d_pr0);
    cudaGetSymbolAddress((void**)&pr1, d_pr1);
    cudaGetSymbolAddress((void**)&p1,  d_p1);
    cudaGetSymbolAddress((void**)&h2,  d_h2);
    cudaGetSymbolAddress((void**)&h3,  d_h3);
    cudaGetSymbolAddress((void**)&e1,  d_e1);
    cudaGetSymbolAddress((void**)&e2,  d_e2);
    cudaGetSymbolAddress((void**)&cnt, d_cnt);
    cudaGetSymbolAddress((void**)&list,d_list);

    // prep
    prep_gw<<<512, 256>>>(gcn_w, gcn_b);
    normc<<<2*NE, 32>>>(centers);

    // BiDGN: gcn + relu + LN fused, both sides in one launch
    {
        GemmArgs a = {};
        a.A[0] = x_l;  a.A[1] = x_r;
        a.W[0] = gw;   a.W[1] = gw;
        a.bias[0] = gb; a.bias[1] = gb;
        a.lng[0] = bln_g; a.lng[1] = bln_g;
        a.lnb[0] = bln_b; a.lnb[1] = bln_b;
        a.C[0] = gl;  a.C[1] = gr;
        gemmF<<<dim3(RR/32, 2), 256>>>(a, TIN, 1);
    }

    for (int i = 0; i < 2; i++){
        const float* Wq = attn_w + (size_t)(i*4+0)*TT*TT;
        const float* Wk = attn_w + (size_t)(i*4+1)*TT*TT;
        const float* Wv = attn_w + (size_t)(i*4+2)*TT*TT;
        const float* Wp = attn_w + (size_t)(i*4+3)*TT*TT;
        const float* bq = attn_b + (i*4+0)*TT;
        const float* bk = attn_b + (i*4+1)*TT;
        const float* bv = attn_b + (i*4+2)*TT;
        const float* bp = attn_b + (i*4+3)*TT;

        {   // Q, K, V in one launch (V input fused: gl - gr); BM=32/BN=128
            GemmArgs a = {};
            a.A[0] = gl; a.A[1] = gr; a.A[2] = gl;
            a.A2[2] = gr;
            a.W[0] = Wq; a.W[1] = Wk; a.W[2] = Wv;
            a.bias[0] = bq; a.bias[1] = bk; a.bias[2] = bv;
            a.C[0] = q; a.C[1] = k; a.C[2] = v;
            gemmH<<<dim3(2, RR/32, 3), 256>>>(a, TT);
        }
        attn35<<<dim3(BB, 2), 256>>>(q, k, v, tl, tr);
        {   // proj + LN + residual for both sides in one launch
            GemmArgs a = {};
            a.A[0] = tl; a.A[1] = tr;
            a.W[0] = Wp; a.W[1] = Wp;
            a.bias[0] = bp; a.bias[1] = bp;
            a.lng[0] = aln_g + (i*2+0)*TT; a.lng[1] = aln_g + (i*2+1)*TT;
            a.lnb[0] = aln_b + (i*2+0)*TT; a.lnb[1] = aln_b + (i*2+1)*TT;
            a.res[0] = gl; a.res[1] = gr;
            a.C[0] = al; a.C[1] = ar;
            gemmF<<<dim3(RR/32, 2), 256>>>(a, TT, 0);
        }

        mclr<<<1, 128>>>(cnt);
        route<<<RR, 128>>>(al, ar, router_w + (size_t)i*TIN*ED, router_b + i*ED,
                           cn + i*NE*ED, e1, e2, cnt, list);
        mkchunks<<<1, 32>>>(cnt);
        moeGrp<<<MOE_BLOCKS, 256>>>(al, ar, expert_w + (size_t)i*NE*TT*TT,
                                    cnt, list, pl0, pl1, pr0, pr1);
        moeC<<<RR, 256>>>(al, ar, pl0, pl1, pr0, pr1,
                          expert_b + (size_t)i*NE*TT, e1, e2,
                          mln_g + (i*2+0)*TT, mln_b + (i*2+0)*TT,
                          mln_g + (i*2+1)*TT, mln_b + (i*2+1)*TT,
                          gl, gr);
    }

    // classifier head
    fc1part<<<dim3(4,40), 256>>>(gl, gr, fc1_w, p1);
    fc1red<<<BB, 256>>>(p1, fc1_b, h2);
    fc2k<<<BB, 32>>>(h2, fc2_w, fc2_b, h3);
    fc3k<<<1, 192>>>(h3, fc3_w, fc3_b, out);
}

// round 13
// speedup vs baseline: 1.2611x; 1.0074x over previous
#include <cuda_runtime.h>
#include <math.h>

// Problem dims
#define BB   64
#define C2   35
#define RR   (BB*C2)     // 2240 rows
#define TIN  512
#define TT   256
#define NE   70
#define ED   32
#define MOE_BLOCKS 296

// ---------------- scratch (device globals; no runtime allocation) ----------------
__device__ __align__(16) float d_gw[TIN*TT];
__device__ __align__(16) float d_gb[TT];
__device__ __align__(16) float d_cn[2*NE*ED];
__device__ __align__(16) float d_gl[RR*TT];
__device__ __align__(16) float d_gr[RR*TT];
__device__ __align__(16) float d_q [RR*TT];
__device__ __align__(16) float d_k [RR*TT];
__device__ __align__(16) float d_v [RR*TT];
__device__ __align__(16) float d_tl[RR*TT];
__device__ __align__(16) float d_tr[RR*TT];
__device__ __align__(16) float d_al[RR*TT];
__device__ __align__(16) float d_ar[RR*TT];
__device__ int   d_e1[RR];
__device__ int   d_e2[RR];
__device__ int   d_cnt[NE];
__device__ int   d_list[NE*RR];
__device__ int2  d_chunks[512];
__device__ int   d_nch;
__device__ __align__(16) float d_pl0[RR*TT];
__device__ __align__(16) float d_pl1[RR*TT];
__device__ __align__(16) float d_pr0[RR*TT];
__device__ __align__(16) float d_pr1[RR*TT];
__device__ __align__(16) float d_p1[40*64*256];
__device__ __align__(16) float d_h2[64*256];
__device__ __align__(16) float d_h3[64*32];

// ---------------- helpers ----------------
__device__ __forceinline__ float warpSumDown(float v){
#pragma unroll
    for (int o=16;o>0;o>>=1) v += __shfl_down_sync(0xffffffffu, v, o);
    return v;
}
__device__ __forceinline__ float warpSumAll(float v){
#pragma unroll
    for (int o=16;o>0;o>>=1) v += __shfl_xor_sync(0xffffffffu, v, o);
    return v;
}
__device__ __forceinline__ float eluf(float x){ return x > 0.f ? x : expm1f(x); }

__device__ __forceinline__ float blockSum256(float v, float* red, float* bc){
    const int n = threadIdx.x, wid = n >> 5;
    float s = warpSumDown(v);
    if ((n & 31) == 0) red[wid] = s;
    __syncthreads();
    if (n < 32){
        float t = (n < 8) ? red[n] : 0.f;
        t = warpSumDown(t);
        if (n == 0) *bc = t;
    }
    __syncthreads();
    float r = *bc;
    __syncthreads();
    return r;
}

// ---------------- prep ----------------
__global__ void prep_gw(const float* __restrict__ GW, const float* __restrict__ GB){
    int idx = blockIdx.x*256 + threadIdx.x;
    d_gw[idx] = GW[idx] + GW[idx + TIN*TT];
    if (idx < TT) d_gb[idx] = -(GB[idx] + GB[idx+TT]);
}

__global__ void normc(const float* __restrict__ C){
    int b = blockIdx.x;
    int lane = threadIdx.x;
    float c = C[b*ED + lane];
    float ss = warpSumAll(c*c);
    d_cn[b*ED + lane] = c / fmaxf(sqrtf(ss), 1e-12f);
}

__global__ void mclr(int* cnt){ if (threadIdx.x < NE) cnt[threadIdx.x] = 0; }

__global__ void mkchunks(const int* __restrict__ cnt){
    if (threadIdx.x == 0){
        int t = 0;
        for (int e = 0; e < NE; e++){
            int n = cnt[e];
            for (int s = 0; s < n; s += 16) d_chunks[t++] = make_int2(e, s);
        }
        d_nch = t;
    }
}

// ---------------- fused GEMM (+bias,+relu,+LN,+residual), z-batched, BM=32/BN=256 --
// Software-pipelined: tile k+1 prefetched into registers during compute of tile k.
struct GemmArgs {
    const float* A[3];
    const float* A2[3];
    const float* W[3];
    const float* bias[3];
    const float* lng[3];
    const float* lnb[3];
    const float* res[3];
    float*       C[3];
};

__global__ __launch_bounds__(256) void gemmF(GemmArgs args, int K, int relu)
{
    const int z = blockIdx.y;
    const float* __restrict__ A    = args.A[z];
    const float* __restrict__ A2   = args.A2[z];
    const float* __restrict__ W    = args.W[z];
    const float* __restrict__ bias = args.bias[z];
    const float* __restrict__ lng  = args.lng[z];
    const float* __restrict__ lnb  = args.lnb[z];
    const float* __restrict__ res  = args.res[z];
    float* __restrict__ C          = args.C[z];

    __shared__ float sA[16][36];
    __shared__ float sB[16][256];

    const int tid = threadIdx.x;
    const int tx = tid & 31, ty = tid >> 5;
    const int m0 = blockIdx.x << 5;
    const int c0 = tx << 2;
    const int ar_ = tid >> 2, akq = (tid & 3) << 2;      // A-load mapping (tid<128)

    float acc[4][8] = {};
    float4 rA;
    float4 rB[4];

    // preload tile 0
    if (tid < 128){
        const size_t off = (size_t)(m0+ar_)*K + akq;
        rA = *(const float4*)(A + off);
        if (A2){
            float4 u = *(const float4*)(A2 + off);
            rA.x -= u.x; rA.y -= u.y; rA.z -= u.z; rA.w -= u.w;
        }
    }
#pragma unroll
    for (int j = 0; j < 4; j++){
        int i = tid + j*256;
        int kk = i >> 6, cq = (i & 63) << 2;
        rB[j] = *(const float4*)(W + (size_t)kk*256 + cq);
    }

    for (int kb = 0; kb < K; kb += 16){
        if (tid < 128){
            sA[akq+0][ar_]=rA.x; sA[akq+1][ar_]=rA.y;
            sA[akq+2][ar_]=rA.z; sA[akq+3][ar_]=rA.w;
        }
#pragma unroll
        for (int j = 0; j < 4; j++){
            int i = tid + j*256;
            int kk = i >> 6, cq = (i & 63) << 2;
            *(float4*)&sB[kk][cq] = rB[j];
        }
        __syncthreads();

        // prefetch next tile
        if (kb + 16 < K){
            if (tid < 128){
                const size_t off = (size_t)(m0+ar_)*K + kb + 16 + akq;
                rA = *(const float4*)(A + off);
                if (A2){
                    float4 u = *(const float4*)(A2 + off);
                    rA.x -= u.x; rA.y -= u.y; rA.z -= u.z; rA.w -= u.w;
                }
            }
#pragma unroll
            for (int j = 0; j < 4; j++){
                int i = tid + j*256;
                int kk = i >> 6, cq = (i & 63) << 2;
                rB[j] = *(const float4*)(W + (size_t)(kb+16+kk)*256 + cq);
            }
        }

#pragma unroll
        for (int k = 0; k < 16; k++){
            float a0 = sA[k][ty*4+0], a1 = sA[k][ty*4+1];
            float a2 = sA[k][ty*4+2], a3 = sA[k][ty*4+3];
            float4 bl = *(float4*)&sB[k][c0];
            float4 bh = *(float4*)&sB[k][c0+128];
            acc[0][0]+=a0*bl.x; acc[0][1]+=a0*bl.y; acc[0][2]+=a0*bl.z; acc[0][3]+=a0*bl.w;
            acc[0][4]+=a0*bh.x; acc[0][5]+=a0*bh.y; acc[0][6]+=a0*bh.z; acc[0][7]+=a0*bh.w;
            acc[1][0]+=a1*bl.x; acc[1][1]+=a1*bl.y; acc[1][2]+=a1*bl.z; acc[1][3]+=a1*bl.w;
            acc[1][4]+=a1*bh.x; acc[1][5]+=a1*bh.y; acc[1][6]+=a1*bh.z; acc[1][7]+=a1*bh.w;
            acc[2][0]+=a2*bl.x; acc[2][1]+=a2*bl.y; acc[2][2]+=a2*bl.z; acc[2][3]+=a2*bl.w;
            acc[2][4]+=a2*bh.x; acc[2][5]+=a2*bh.y; acc[2][6]+=a2*bh.z; acc[2][7]+=a2*bh.w;
            acc[3][0]+=a3*bl.x; acc[3][1]+=a3*bl.y; acc[3][2]+=a3*bl.z; acc[3][3]+=a3*bl.w;
            acc[3][4]+=a3*bh.x; acc[3][5]+=a3*bh.y; acc[3][6]+=a3*bh.z; acc[3][7]+=a3*bh.w;
        }
        __syncthreads();
    }

    float4 bl = *(const float4*)(bias + c0);
    float4 bh = *(const float4*)(bias + c0 + 128);
    float bcol[8] = {bl.x,bl.y,bl.z,bl.w,bh.x,bh.y,bh.z,bh.w};

    float gcol[8], bbcol[8];
    if (lng){
        float4 g0 = *(const float4*)(lng + c0);
        float4 g1 = *(const float4*)(lng + c0 + 128);
        float4 q0 = *(const float4*)(lnb + c0);
        float4 q1 = *(const float4*)(lnb + c0 + 128);
        gcol[0]=g0.x; gcol[1]=g0.y; gcol[2]=g0.z; gcol[3]=g0.w;
        gcol[4]=g1.x; gcol[5]=g1.y; gcol[6]=g1.z; gcol[7]=g1.w;
        bbcol[0]=q0.x; bbcol[1]=q0.y; bbcol[2]=q0.z; bbcol[3]=q0.w;
        bbcol[4]=q1.x; bbcol[5]=q1.y; bbcol[6]=q1.z; bbcol[7]=q1.w;
    }

#pragma unroll
    for (int i=0;i<4;i++){
        const int row = m0 + ty*4 + i;
        float v[8];
#pragma unroll
        for (int j=0;j<8;j++){
            v[j] = acc[i][j] + bcol[j];
            if (relu) v[j] = fmaxf(v[j], 0.f);
        }
        if (lng){
            float s = 0.f;
#pragma unroll
            for (int j=0;j<8;j++) s += v[j];
            float mean = warpSumAll(s) * (1.f/256.f);
            float sq = 0.f;
#pragma unroll
            for (int j=0;j<8;j++){ float d = v[j]-mean; sq += d*d; }
            float inv = rsqrtf(warpSumAll(sq) * (1.f/256.f) + 1e-5f);
#pragma unroll
            for (int j=0;j<8;j++) v[j] = (v[j]-mean)*inv*gcol[j] + bbcol[j];
            if (res){
                float4 r0 = *(const float4*)(res + (size_t)row*256 + c0);
                float4 r1 = *(const float4*)(res + (size_t)row*256 + c0 + 128);
                v[0]+=r0.x; v[1]+=r0.y; v[2]+=r0.z; v[3]+=r0.w;
                v[4]+=r1.x; v[5]+=r1.y; v[6]+=r1.z; v[7]+=r1.w;
            }
        }
        *(float4*)(C + (size_t)row*256 + c0)       = make_float4(v[0],v[1],v[2],v[3]);
        *(float4*)(C + (size_t)row*256 + c0 + 128) = make_float4(v[4],v[5],v[6],v[7]);
    }
}

// ---------------- plain GEMM, BM=32/BN=128 (no LN), pipelined ----------------
__global__ __launch_bounds__(256) void gemmH(GemmArgs args, int K)
{
    const int z = blockIdx.z;
    const float* __restrict__ A    = args.A[z];
    const float* __restrict__ A2   = args.A2[z];
    const float* __restrict__ W    = args.W[z];
    const float* __restrict__ bias = args.bias[z];
    float* __restrict__ C          = args.C[z];

    __shared__ float sA[16][36];
    __shared__ float sB[16][128];

    const int tid = threadIdx.x;
    const int tx = tid & 31, ty = tid >> 5;
    const int m0 = blockIdx.y << 5;
    const int n0 = blockIdx.x << 7;
    const int c0 = tx << 2;
    const int ar_ = tid >> 2, akq = (tid & 3) << 2;

    float acc[4][4] = {};
    float4 rA;
    float4 rB[2];

    if (tid < 128){
        const size_t off = (size_t)(m0+ar_)*K + akq;
        rA = *(const float4*)(A + off);
        if (A2){
            float4 u = *(const float4*)(A2 + off);
            rA.x -= u.x; rA.y -= u.y; rA.z -= u.z; rA.w -= u.w;
        }
    }
#pragma unroll
    for (int j = 0; j < 2; j++){
        int i = tid + j*256;
        int kk = i >> 5, cq = (i & 31) << 2;
        rB[j] = *(const float4*)(W + (size_t)kk*256 + n0 + cq);
    }

    for (int kb = 0; kb < K; kb += 16){
        if (tid < 128){
            sA[akq+0][ar_]=rA.x; sA[akq+1][ar_]=rA.y;
            sA[akq+2][ar_]=rA.z; sA[akq+3][ar_]=rA.w;
        }
#pragma unroll
        for (int j = 0; j < 2; j++){
            int i = tid + j*256;
            int kk = i >> 5, cq = (i & 31) << 2;
            *(float4*)&sB[kk][cq] = rB[j];
        }
        __syncthreads();

        if (kb + 16 < K){
            if (tid < 128){
                const size_t off = (size_t)(m0+ar_)*K + kb + 16 + akq;
                rA = *(const float4*)(A + off);
                if (A2){
                    float4 u = *(const float4*)(A2 + off);
                    rA.x -= u.x; rA.y -= u.y; rA.z -= u.z; rA.w -= u.w;
                }
            }
#pragma unroll
            for (int j = 0; j < 2; j++){
                int i = tid + j*256;
                int kk = i >> 5, cq = (i & 31) << 2;
                rB[j] = *(const float4*)(W + (size_t)(kb+16+kk)*256 + n0 + cq);
            }
        }

#pragma unroll
        for (int k = 0; k < 16; k++){
            float a0 = sA[k][ty*4+0], a1 = sA[k][ty*4+1];
            float a2 = sA[k][ty*4+2], a3 = sA[k][ty*4+3];
            float4 b = *(float4*)&sB[k][c0];
            acc[0][0]+=a0*b.x; acc[0][1]+=a0*b.y; acc[0][2]+=a0*b.z; acc[0][3]+=a0*b.w;
            acc[1][0]+=a1*b.x; acc[1][1]+=a1*b.y; acc[1][2]+=a1*b.z; acc[1][3]+=a1*b.w;
            acc[2][0]+=a2*b.x; acc[2][1]+=a2*b.y; acc[2][2]+=a2*b.z; acc[2][3]+=a2*b.w;
            acc[3][0]+=a3*b.x; acc[3][1]+=a3*b.y; acc[3][2]+=a3*b.z; acc[3][3]+=a3*b.w;
        }
        __syncthreads();
    }

    float4 bv = *(const float4*)(bias + n0 + c0);
#pragma unroll
    for (int i=0;i<4;i++){
        const int row = m0 + ty*4 + i;
        *(float4*)(C + (size_t)row*256 + n0 + c0) =
            make_float4(acc[i][0]+bv.x, acc[i][1]+bv.y, acc[i][2]+bv.z, acc[i][3]+bv.w);
    }
}

// ---------------- attention (35 tokens per batch, 1 head), y-split ----------------
__global__ __launch_bounds__(256) void attn35(
    const float* __restrict__ Q, const float* __restrict__ Km,
    const float* __restrict__ V, float* __restrict__ TL, float* __restrict__ TR)
{
    __shared__ float sk[35*256];
    __shared__ float S[35*36];
    const int b = blockIdx.x, tid = threadIdx.x;
    const int r0 = blockIdx.y * 18, r1 = min(35, r0 + 18);
    const size_t base = (size_t)b * (35*256);
    for (int i=tid;i<35*256;i+=256) sk[i] = Km[base+i];
    __syncthreads();
    for (int e=tid;e<1225;e+=256){
        int r = e/35, c = e - r*35;
        const float* qr = Q + base + r*256;
        const float* kr = &sk[c*256];
        float s = 0.f;
#pragma unroll 8
        for (int k=0;k<256;k++) s += qr[k]*kr[k];
        S[r*36+c] = s * 0.0625f;
    }
    __syncthreads();
    if (tid < 35){
        float mx = -1e30f;
        for (int c=0;c<35;c++) mx = fmaxf(mx, S[tid*36+c]);
        float sum = 0.f;
        for (int c=0;c<35;c++){ float e = expf(S[tid*36+c]-mx); S[tid*36+c]=e; sum+=e; }
        float inv = 1.f/sum;
        for (int c=0;c<35;c++) S[tid*36+c] *= inv;
    }
    __syncthreads();
    for (int i=tid;i<35*256;i+=256) sk[i] = V[base+i];
    __syncthreads();
    const int n = tid;
    for (int r=r0;r<r1;r++){
        float al=0.f, ar=0.f;
#pragma unroll
        for (int k=0;k<35;k++){
            float vv = sk[k*256+n];
            al += S[r*36+k]*vv;
            ar += S[k*36+r]*vv;
        }
        TL[base + r*256 + n] = al;
        TR[base + r*256 + n] = ar;
    }
}

// ---------------- router + cosine top-2; appends to expert lists ----------------
__global__ __launch_bounds__(128) void route(
    const float* __restrict__ AL, const float* __restrict__ AR,
    const float* __restrict__ RW, const float* __restrict__ RB,
    const float* __restrict__ CN, int* __restrict__ E1, int* __restrict__ E2,
    int* __restrict__ cnt, int* __restrict__ list)
{
    __shared__ float sx[512];
    __shared__ float part[4][32];
    __shared__ float sz[32];
    __shared__ float ssim[70];
    const int row = blockIdx.x, tid = threadIdx.x;
    for (int i=tid;i<256;i+=128){
        sx[i]     = AL[(size_t)row*256+i];
        sx[256+i] = AR[(size_t)row*256+i];
    }
    __syncthreads();
    {
        const int o = tid & 31, p = tid >> 5;
        float acc = (p == 0) ? RB[o] : 0.f;
        for (int k = p*128; k < p*128+128; k++) acc += sx[k]*RW[k*32+o];
        part[p][o] = acc;
    }
    __syncthreads();
    if (tid < 32){
        float acc = part[0][tid]+part[1][tid]+part[2][tid]+part[3][tid];
        float n2 = warpSumAll(acc*acc);
        sz[tid] = acc / fmaxf(sqrtf(n2), 1e-12f);
    }
    __syncthreads();
    if (tid < 70){
        const float* c = CN + tid*32;
        float s = 0.f;
#pragma unroll
        for (int j=0;j<32;j++) s += sz[j]*c[j];
        ssim[tid] = s;
    }
    __syncthreads();
    if (tid == 0){
        float m1=-2.f; int i1=0;
        for (int e=0;e<70;e++) if (ssim[e] > m1){ m1=ssim[e]; i1=e; }
        float m2=-2.f; int i2=(i1==0)?1:0;
        for (int e=0;e<70;e++) if (e!=i1 && ssim[e] > m2){ m2=ssim[e]; i2=e; }
        E1[row]=i1; E2[row]=i2;
        int p1 = atomicAdd(&cnt[i1], 1);
        list[i1*RR + p1] = row;                 // slot 0
        int p2 = atomicAdd(&cnt[i2], 1);
        list[i2*RR + p2] = row | (1 << 15);     // slot 1
    }
}

// ---------------- grouped MoE GEMM over FLAT chunk list, pipelined ----------------
__global__ __launch_bounds__(256) void moeGrp(
    const float* __restrict__ AL, const float* __restrict__ AR,
    const float* __restrict__ EW,
    const int* __restrict__ cnt, const int* __restrict__ list,
    float* __restrict__ PL0, float* __restrict__ PL1,
    float* __restrict__ PR0, float* __restrict__ PR1)
{
    __shared__ float sA[16][36];
    __shared__ float sB[16][256];
    __shared__ int sent[16];

    const int tid = threadIdx.x;
    const int tx = tid & 31, ty = tid >> 5;
    const int c0 = tx << 2;
    const int ar_ = tid >> 2, akq = (tid & 3) << 2;
    const int nch = d_nch;

    for (int ci = blockIdx.x; ci < nch; ci += gridDim.x){
        const int2 ch = d_chunks[ci];
        const int e = ch.x;
        const int n = cnt[e];
        const float* __restrict__ W = EW + (size_t)e*65536;

        __syncthreads();
        if (tid < 16){
            int idx = ch.y + tid;
            sent[tid] = (idx < n) ? list[e*RR + idx] : -1;
        }
        __syncthreads();

        float acc[4][8] = {};
        float4 rA = make_float4(0.f,0.f,0.f,0.f);
        float4 rB[4];

        // preload kb = 0
        if (tid < 128){
            int ent = sent[ar_ & 15];
            if (ent >= 0){
                int row = ent & 0x7FFF;
                const float* src = (ar_ < 16) ? AL : AR;
                rA = *(const float4*)(src + (size_t)row*256 + akq);
            }
        }
#pragma unroll
        for (int j = 0; j < 4; j++){
            int i = tid + j*256;
            int kk = i >> 6, cq = (i & 63) << 2;
            rB[j] = *(const float4*)(W + (size_t)kk*256 + cq);
        }

        for (int kb = 0; kb < 256; kb += 16){
            if (tid < 128){
                sA[akq+0][ar_]=rA.x; sA[akq+1][ar_]=rA.y;
                sA[akq+2][ar_]=rA.z; sA[akq+3][ar_]=rA.w;
            }
#pragma unroll
            for (int j = 0; j < 4; j++){
                int i = tid + j*256;
                int kk = i >> 6, cq = (i & 63) << 2;
                *(float4*)&sB[kk][cq] = rB[j];
            }
            __syncthreads();

            if (kb + 16 < 256){
                if (tid < 128){
                    int ent = sent[ar_ & 15];
                    rA = make_float4(0.f,0.f,0.f,0.f);
                    if (ent >= 0){
                        int row = ent & 0x7FFF;
                        const float* src = (ar_ < 16) ? AL : AR;
                        rA = *(const float4*)(src + (size_t)row*256 + kb + 16 + akq);
                    }
                }
#pragma unroll
                for (int j = 0; j < 4; j++){
                    int i = tid + j*256;
                    int kk = i >> 6, cq = (i & 63) << 2;
                    rB[j] = *(const float4*)(W + (size_t)(kb+16+kk)*256 + cq);
                }
            }

#pragma unroll
            for (int k = 0; k < 16; k++){
                float a0 = sA[k][ty*4+0], a1 = sA[k][ty*4+1];
                float a2 = sA[k][ty*4+2], a3 = sA[k][ty*4+3];
                float4 bl = *(float4*)&sB[k][c0];
                float4 bh = *(float4*)&sB[k][c0+128];
                acc[0][0]+=a0*bl.x; acc[0][1]+=a0*bl.y; acc[0][2]+=a0*bl.z; acc[0][3]+=a0*bl.w;
                acc[0][4]+=a0*bh.x; acc[0][5]+=a0*bh.y; acc[0][6]+=a0*bh.z; acc[0][7]+=a0*bh.w;
                acc[1][0]+=a1*bl.x; acc[1][1]+=a1*bl.y; acc[1][2]+=a1*bl.z; acc[1][3]+=a1*bl.w;
                acc[1][4]+=a1*bh.x; acc[1][5]+=a1*bh.y; acc[1][6]+=a1*bh.z; acc[1][7]+=a1*bh.w;
                acc[2][0]+=a2*bl.x; acc[2][1]+=a2*bl.y; acc[2][2]+=a2*bl.z; acc[2][3]+=a2*bl.w;
                acc[2][4]+=a2*bh.x; acc[2][5]+=a2*bh.y; acc[2][6]+=a2*bh.z; acc[2][7]+=a2*bh.w;
                acc[3][0]+=a3*bl.x; acc[3][1]+=a3*bl.y; acc[3][2]+=a3*bl.z; acc[3][3]+=a3*bl.w;
                acc[3][4]+=a3*bh.x; acc[3][5]+=a3*bh.y; acc[3][6]+=a3*bh.z; acc[3][7]+=a3*bh.w;
            }
            __syncthreads();
        }

#pragma unroll
        for (int i=0;i<4;i++){
            int r = ty*4 + i;
            int ent = sent[r & 15];
            if (ent >= 0){
                int row = ent & 0x7FFF, slot = ent >> 15;
                float* dst = (r < 16) ? (slot ? PL1 : PL0) : (slot ? PR1 : PR0);
                *(float4*)(dst + (size_t)row*256 + c0) =
                    make_float4(acc[i][0],acc[i][1],acc[i][2],acc[i][3]);
                *(float4*)(dst + (size_t)row*256 + c0 + 128) =
                    make_float4(acc[i][4],acc[i][5],acc[i][6],acc[i][7]);
            }
        }
    }
}

// ---------------- MoE combine: partials + bias -> LN -> +residual (both sides) ----
__global__ __launch_bounds__(256) void moeC(
    const float* __restrict__ AL, const float* __restrict__ AR,
    const float* __restrict__ PL0, const float* __restrict__ PL1,
    const float* __restrict__ PR0, const float* __restrict__ PR1,
    const float* __restrict__ EB,
    const int* __restrict__ E1, const int* __restrict__ E2,
    const float* __restrict__ g0, const float* __restrict__ b0,
    const float* __restrict__ g1, const float* __restrict__ b1,
    float* __restrict__ GL, float* __restrict__ GR)
{
    __shared__ float red[8];
    __shared__ float bc;
    const int row = blockIdx.x, n = threadIdx.x;
    const size_t off = (size_t)row*256 + n;
    const int e1 = E1[row], e2 = E2[row];
    const float bb = EB[e1*256+n] + EB[e2*256+n];
    const float a  = AL[off], b = AR[off];
    float ml = PL0[off] + PL1[off] + bb;
    float mr = PR0[off] + PR1[off] + bb;

    float mean = blockSum256(ml, red, &bc) * (1.f/256.f);
    float dd = ml - mean;
    float var = blockSum256(dd*dd, red, &bc) * (1.f/256.f);
    GL[off] = dd * rsqrtf(var + 1e-5f) * g0[n] + b0[n] + a;

    mean = blockSum256(mr, red, &bc) * (1.f/256.f);
    dd = mr - mean;
    var = blockSum256(dd*dd, red, &bc) * (1.f/256.f);
    GR[off] = dd * rsqrtf(var + 1e-5f) * g1[n] + b1[n] + b;
}

// ---------------- classifier fc1: split-K partial GEMM ----------------
__global__ __launch_bounds__(256) void fc1part(
    const float* __restrict__ GL, const float* __restrict__ GR,
    const float* __restrict__ W, float* __restrict__ P)
{
    __shared__ float As[16][64];
    __shared__ float Bs[16][64];
    const int s = blockIdx.y;
    const float* A = (s < 20) ? (GL + s*448) : (GR + (s-20)*448);
    const int n0 = blockIdx.x << 6;
    const int wk0 = s*448;
    const int tid = threadIdx.x;
    const int tx = tid & 15, ty = tid >> 4;
    const int lar = tid >> 2, laq = tid & 3;
    const int lbk = tid >> 4, lbc = tid & 15;
    float acc[4][4] = {};
    for (int kb = 0; kb < 448; kb += 16){
        float4 av = *(const float4*)(A + (size_t)lar*8960 + kb + laq*4);
        As[laq*4+0][lar] = av.x; As[laq*4+1][lar] = av.y;
        As[laq*4+2][lar] = av.z; As[laq*4+3][lar] = av.w;
        *(float4*)&Bs[lbk][lbc*4] =
            *(const float4*)(W + (size_t)(wk0+kb+lbk)*256 + n0 + lbc*4);
        __syncthreads();
#pragma unroll
        for (int k = 0; k < 16; k++){
            float4 a = *(const float4*)&As[k][ty*4];
            float4 b = *(const float4*)&Bs[k][tx*4];
            acc[0][0] += a.x*b.x; acc[0][1] += a.x*b.y; acc[0][2] += a.x*b.z; acc[0][3] += a.x*b.w;
            acc[1][0] += a.y*b.x; acc[1][1] += a.y*b.y; acc[1][2] += a.y*b.z; acc[1][3] += a.y*b.w;
            acc[2][0] += a.z*b.x; acc[2][1] += a.z*b.y; acc[2][2] += a.z*b.z; acc[2][3] += a.z*b.w;
            acc[3][0] += a.w*b.x; acc[3][1] += a.w*b.y; acc[3][2] += a.w*b.z; acc[3][3] += a.w*b.w;
        }
        __syncthreads();
    }
#pragma unroll
    for (int i=0;i<4;i++)
#pragma unroll
        for (int j=0;j<4;j++)
            P[(size_t)s*16384 + (size_t)(ty*4+i)*256 + n0 + tx*4 + j] = acc[i][j];
}

__global__ __launch_bounds__(256) void fc1red(
    const float* __restrict__ P, const float* __restrict__ bias,
    float* __restrict__ H2)
{
    const int b = blockIdx.x, n = threadIdx.x;
    float acc = bias[n];
    for (int s=0;s<40;s++) acc += P[(size_t)s*16384 + b*256 + n];
    H2[b*256+n] = eluf(acc);
}

__global__ void fc2k(const float* __restrict__ H2, const float* __restrict__ W,
                     const float* __restrict__ bias, float* __restrict__ H3)
{
    const int b = blockIdx.x, j = threadIdx.x;
    float acc = bias[j];
    for (int k=0;k<256;k++) acc += H2[b*256+k] * W[k*32+j];
    H3[b*32+j] = eluf(acc);
}

__global__ void fc3k(const float* __restrict__ H3, const float* __restrict__ W,
                     const float* __restrict__ bias, float* __restrict__ OUT)
{
    const int tid = threadIdx.x;
    const int b = tid/3, c = tid%3;
    float acc = bias[c];
#pragma unroll
    for (int k=0;k<32;k++) acc += H3[b*32+k] * W[k*3+c];
    OUT[b*3+c] = acc;
}

// ---------------- host launch sequence ----------------
extern "C" void kernel_launch(void* const* d_in, const int* in_sizes, int n_in,
                              void* d_out, int out_size)
{
    const float* x_l      = (const float*)d_in[0];
    const float* x_r      = (const float*)d_in[1];
    const float* gcn_w    = (const float*)d_in[2];
    const float* gcn_b    = (const float*)d_in[3];
    const float* bln_g    = (const float*)d_in[4];
    const float* bln_b    = (const float*)d_in[5];
    const float* attn_w   = (const float*)d_in[6];
    const float* attn_b   = (const float*)d_in[7];
    const float* aln_g    = (const float*)d_in[8];
    const float* aln_b    = (const float*)d_in[9];
    const float* router_w = (const float*)d_in[10];
    const float* router_b = (const float*)d_in[11];
    const float* centers  = (const float*)d_in[12];
    const float* expert_w = (const float*)d_in[13];
    const float* expert_b = (const float*)d_in[14];
    const float* mln_g    = (const float*)d_in[15];
    const float* mln_b    = (const float*)d_in[16];
    const float* fc1_w    = (const float*)d_in[17];
    const float* fc1_b    = (const float*)d_in[18];
    const float* fc2_w    = (const float*)d_in[19];
    const float* fc2_b    = (const float*)d_in[20];
    const float* fc3_w    = (const float*)d_in[21];
    const float* fc3_b    = (const float*)d_in[22];
    float* out = (float*)d_out;

    float *gw, *gb, *cn, *gl, *gr, *q, *k, *v, *tl, *tr, *al, *ar;
    float *pl0, *pl1, *pr0, *pr1, *p1, *h2, *h3;
    int *e1, *e2, *cnt, *list;
    cudaGetSymbolAddress((void**)&gw,  d_gw);
    cudaGetSymbolAddress((void**)&gb,  d_gb);
    cudaGetSymbolAddress((void**)&cn,  d_cn);
    cudaGetSymbolAddress((void**)&gl,  d_gl);
    cudaGetSymbolAddress((void**)&gr,  d_gr);
    cudaGetSymbolAddress((void**)&q,   d_q);
    cudaGetSymbolAddress((void**)&k,   d_k);
    cudaGetSymbolAddress((void**)&v,   d_v);
    cudaGetSymbolAddress((void**)&tl,  d_tl);
    cudaGetSymbolAddress((void**)&tr,  d_tr);
    cudaGetSymbolAddress((void**)&al,  d_al);
    cudaGetSymbolAddress((void**)&ar,  d_ar);
    cudaGetSymbolAddress((void**)&pl0, d_pl0);
    cudaGetSymbolAddress((void**)&pl1, d_pl1);
    cudaGetSymbolAddress((void**)&pr0, d_pr0);
    cudaGetSymbolAddress((void**)&pr1, d_pr1);
    cudaGetSymbolAddress((void**)&p1,  d_p1);
    cudaGetSymbolAddress((void**)&h2,  d_h2);
    cudaGetSymbolAddress((void**)&h3,  d_h3);
    cudaGetSymbolAddress((void**)&e1,  d_e1);
    cudaGetSymbolAddress((void**)&e2,  d_e2);
    cudaGetSymbolAddress((void**)&cnt, d_cnt);
    cudaGetSymbolAddress((void**)&list,d_list);

    // prep
    prep_gw<<<512, 256>>>(gcn_w, gcn_b);
    normc<<<2*NE, 32>>>(centers);

    // BiDGN: gcn + relu + LN fused, both sides in one launch
    {
        GemmArgs a = {};
        a.A[0] = x_l;  a.A[1] = x_r;
        a.W[0] = gw;   a.W[1] = gw;
        a.bias[0] = gb; a.bias[1] = gb;
        a.lng[0] = bln_g; a.lng[1] = bln_g;
        a.lnb[0] = bln_b; a.lnb[1] = bln_b;
        a.C[0] = gl;  a.C[1] = gr;
        gemmF<<<dim3(RR/32, 2), 256>>>(a, TIN, 1);
    }

    for (int i = 0; i < 2; i++){
        const float* Wq = attn_w + (size_t)(i*4+0)*TT*TT;
        const float* Wk = attn_w + (size_t)(i*4+1)*TT*TT;
        const float* Wv = attn_w + (size_t)(i*4+2)*TT*TT;
        const float* Wp = attn_w + (size_t)(i*4+3)*TT*TT;
        const float* bq = attn_b + (i*4+0)*TT;
        const float* bk = attn_b + (i*4+1)*TT;
        const float* bv = attn_b + (i*4+2)*TT;
        const float* bp = attn_b + (i*4+3)*TT;

        {   // Q, K, V in one launch (V input fused: gl - gr); BM=32/BN=128
            GemmArgs a = {};
            a.A[0] = gl; a.A[1] = gr; a.A[2] = gl;
            a.A2[2] = gr;
            a.W[0] = Wq; a.W[1] = Wk; a.W[2] = Wv;
            a.bias[0] = bq; a.bias[1] = bk; a.bias[2] = bv;
            a.C[0] = q; a.C[1] = k; a.C[2] = v;
            gemmH<<<dim3(2, RR/32, 3), 256>>>(a, TT);
        }
        attn35<<<dim3(BB, 2), 256>>>(q, k, v, tl, tr);
        {   // proj + LN + residual for both sides in one launch
            GemmArgs a = {};
            a.A[0] = tl; a.A[1] = tr;
            a.W[0] = Wp; a.W[1] = Wp;
            a.bias[0] = bp; a.bias[1] = bp;
            a.lng[0] = aln_g + (i*2+0)*TT; a.lng[1] = aln_g + (i*2+1)*TT;
            a.lnb[0] = aln_b + (i*2+0)*TT; a.lnb[1] = aln_b + (i*2+1)*TT;
            a.res[0] = gl; a.res[1] = gr;
            a.C[0] = al; a.C[1] = ar;
            gemmF<<<dim3(RR/32, 2), 256>>>(a, TT, 0);
        }

        mclr<<<1, 128>>>(cnt);
        route<<<RR, 128>>>(al, ar, router_w + (size_t)i*TIN*ED, router_b + i*ED,
                           cn + i*NE*ED, e1, e2, cnt, list);
        mkchunks<<<1, 32>>>(cnt);
        moeGrp<<<MOE_BLOCKS, 256>>>(al, ar, expert_w + (size_t)i*NE*TT*TT,
                                    cnt, list, pl0, pl1, pr0, pr1);
        moeC<<<RR, 256>>>(al, ar, pl0, pl1, pr0, pr1,
                          expert_b + (size_t)i*NE*TT, e1, e2,
                          mln_g + (i*2+0)*TT, mln_b + (i*2+0)*TT,
                          mln_g + (i*2+1)*TT, mln_b + (i*2+1)*TT,
                          gl, gr);
    }

    // classifier head
    fc1part<<<dim3(4,40), 256>>>(gl, gr, fc1_w, p1);
    fc1red<<<BB, 256>>>(p1, fc1_b, h2);
    fc2k<<<BB, 32>>>(h2, fc2_w, fc2_b, h3);
    fc3k<<<1, 192>>>(h3, fc3_w, fc3_b, out);
}